// round 1
// baseline (speedup 1.0000x reference)
#include <cuda_runtime.h>
#include <math.h>

#define E_   64
#define KTOP 4
#define H_   2048
#define I_   1536
#define GS_  128
#define T_   1024
#define C_   128

#define BM 64
#define BN 128
#define BK 64
#define BMP 68
#define BNP 132

// ---------------- scratch (device globals: no allocations allowed) ----------
__device__ int   g_ti[T_ * KTOP];
__device__ float g_tw[T_ * KTOP];
__device__ int   g_cnt[E_];
__device__ int   g_slotTok[E_ * C_];
__device__ float g_slotW[E_ * C_];
__device__ float g_hbuf[(size_t)E_ * C_ * I_];   // expert SwiGLU intermediates
__device__ float g_hsh[(size_t)T_ * I_];         // shared-expert intermediates

// ---------------- FP4 E2M1 decode (arithmetic, branch-free-ish) -------------
__device__ __forceinline__ float fp4_to_f32(unsigned v) {
    unsigned s = (v & 8u) << 28;
    unsigned e = (v >> 1) & 3u;
    unsigned m = v & 1u;
    unsigned bits = e ? (((126u + e) << 23) | (m << 22))
                      : (m ? 0x3F000000u : 0u);
    return __uint_as_float(bits | s);
}

// ---------------- routing: logits -> top4 -> softmax over top4 --------------
__global__ void routing_kernel(const float* __restrict__ x,
                               const float* __restrict__ gw) {
    __shared__ float lg[8][E_];
    int tid  = threadIdx.x;
    int tok0 = blockIdx.x * 8;

    // two (token, expert) pairs per thread: 8 tokens x 64 experts = 512 dots
    #pragma unroll
    for (int p = 0; p < 2; p++) {
        int pair = tid + p * 256;
        int tk = pair >> 6;
        int e  = pair & 63;
        const float* xr = x  + (size_t)(tok0 + tk) * H_;
        const float* wr = gw + (size_t)e * H_;
        float acc = 0.f;
        for (int h = 0; h < H_; h += 4) {
            float4 a = *(const float4*)(xr + h);
            float4 b = *(const float4*)(wr + h);
            acc += a.x * b.x + a.y * b.y + a.z * b.z + a.w * b.w;
        }
        lg[tk][e] = acc;
    }
    __syncthreads();

    if (tid < 8) {
        int t = tok0 + tid;
        unsigned long long used = 0ull;
        float v[KTOP]; int id[KTOP];
        #pragma unroll
        for (int k = 0; k < KTOP; k++) {
            float best = -INFINITY; int bi = 0;
            for (int e = 0; e < E_; e++) {
                if (!((used >> e) & 1ull) && lg[tid][e] > best) { best = lg[tid][e]; bi = e; }
            }
            v[k] = best; id[k] = bi; used |= 1ull << bi;
        }
        float mx = v[0];
        float w[KTOP], sum = 0.f;
        #pragma unroll
        for (int k = 0; k < KTOP; k++) { w[k] = expf(v[k] - mx); sum += w[k]; }
        #pragma unroll
        for (int k = 0; k < KTOP; k++) {
            g_ti[t * KTOP + k] = id[k];
            g_tw[t * KTOP + k] = w[k] / sum;
        }
    }
}

// ---------------- dispatch: stable per-expert rank (matches reference) ------
__global__ void dispatch_kernel() {
    __shared__ int sti[T_ * KTOP];
    for (int i = threadIdx.x; i < T_ * KTOP; i += blockDim.x) sti[i] = g_ti[i];
    __syncthreads();
    int e = threadIdx.x;
    if (e < E_) {
        int c = 0;
        for (int a = 0; a < T_ * KTOP; a++) {
            if (sti[a] == e) {
                if (c < C_) {
                    g_slotTok[e * C_ + c] = a >> 2;   // token = a / K
                    g_slotW[e * C_ + c]   = g_tw[a];
                }
                c++;
            }
        }
        g_cnt[e] = c < C_ ? c : C_;
    }
}

// ---------------- GEMM 1: h = silu(x Wg^T) * (x Wu^T), FP4 dequant ----------
template <bool SHARED>
__global__ void gemm1_kernel(const float* __restrict__ x,
                             const int* __restrict__ gp, const float* __restrict__ gs,
                             const int* __restrict__ up, const float* __restrict__ us) {
    extern __shared__ float sm[];
    float* As = sm;                          // [BK][BMP]
    float* Bg = sm + BK * BMP;               // [BK][BNP]
    float* Bu = Bg + BK * BNP;               // [BK][BNP]

    int e     = SHARED ? 0 : blockIdx.z;
    int nrows = SHARED ? T_ : g_cnt[e];
    int r0    = blockIdx.x * BM;
    if (r0 >= nrows) return;
    int j0  = blockIdx.y * BN;
    int tid = threadIdx.x;

    // A-loader mapping
    int a_m = tid >> 2, a_c = tid & 3;
    int a_r = r0 + a_m;
    bool a_valid = a_r < nrows;
    const float* a_ptr = x;
    if (a_valid) {
        int tok = SHARED ? a_r : g_slotTok[e * C_ + a_r];
        a_ptr = x + (size_t)tok * H_;
    }

    // B-loader mapping
    int bj = tid >> 1, bh = tid & 1;
    size_t wrow = ((size_t)e * I_ + (j0 + bj)) * (H_ / 8);
    size_t srow_base = (size_t)e * (H_ / GS_);

    int tn = tid & 15, tm = tid >> 4;

    float accg[4][8], accu[4][8];
    #pragma unroll
    for (int i = 0; i < 4; i++)
        #pragma unroll
        for (int j = 0; j < 8; j++) { accg[i][j] = 0.f; accu[i][j] = 0.f; }

    for (int kk = 0; kk < H_; kk += BK) {
        // stage A (transposed)
        #pragma unroll
        for (int i = 0; i < 4; i++) {
            int f4 = a_c * 4 + i;
            float4 v = a_valid ? *(const float4*)(a_ptr + kk + f4 * 4)
                               : make_float4(0.f, 0.f, 0.f, 0.f);
            int k = f4 * 4;
            As[(k + 0) * BMP + a_m] = v.x;
            As[(k + 1) * BMP + a_m] = v.y;
            As[(k + 2) * BMP + a_m] = v.z;
            As[(k + 3) * BMP + a_m] = v.w;
        }
        // stage B: dequant gate & up (64 k-values fit one scale group: kk%128 in {0,64})
        {
            int grp = kk >> 7;
            float sgv = gs[(srow_base + grp) * I_ + j0 + bj];
            float suv = us[(srow_base + grp) * I_ + j0 + bj];
            int4 wg = *((const int4*)(gp + wrow + (kk >> 3)) + bh);
            int4 wu = *((const int4*)(up + wrow + (kk >> 3)) + bh);
            unsigned ag[4] = {(unsigned)wg.x, (unsigned)wg.y, (unsigned)wg.z, (unsigned)wg.w};
            unsigned au[4] = {(unsigned)wu.x, (unsigned)wu.y, (unsigned)wu.z, (unsigned)wu.w};
            int kb = bh * 32;
            #pragma unroll
            for (int q = 0; q < 4; q++) {
                #pragma unroll
                for (int t2 = 0; t2 < 8; t2++) {
                    int krow = kb + q * 8 + t2;
                    Bg[krow * BNP + bj] = fp4_to_f32((ag[q] >> (4 * t2)) & 0xFu) * sgv;
                    Bu[krow * BNP + bj] = fp4_to_f32((au[q] >> (4 * t2)) & 0xFu) * suv;
                }
            }
        }
        __syncthreads();

        #pragma unroll 8
        for (int k = 0; k < BK; k++) {
            float4 av  = *(const float4*)&As[k * BMP + tm * 4];
            const float* bgr = &Bg[k * BNP + tn * 8];
            const float* bur = &Bu[k * BNP + tn * 8];
            float4 bg0 = *(const float4*)bgr;
            float4 bg1 = *(const float4*)(bgr + 4);
            float4 bu0 = *(const float4*)bur;
            float4 bu1 = *(const float4*)(bur + 4);
            float am[4]  = {av.x, av.y, av.z, av.w};
            float bgv[8] = {bg0.x, bg0.y, bg0.z, bg0.w, bg1.x, bg1.y, bg1.z, bg1.w};
            float buv[8] = {bu0.x, bu0.y, bu0.z, bu0.w, bu1.x, bu1.y, bu1.z, bu1.w};
            #pragma unroll
            for (int i = 0; i < 4; i++)
                #pragma unroll
                for (int j = 0; j < 8; j++) {
                    accg[i][j] = fmaf(am[i], bgv[j], accg[i][j]);
                    accu[i][j] = fmaf(am[i], buv[j], accu[i][j]);
                }
        }
        __syncthreads();
    }

    // epilogue: SwiGLU, store intermediates
    #pragma unroll
    for (int i = 0; i < 4; i++) {
        int r = r0 + tm * 4 + i;
        if (r >= nrows) continue;
        float* dst = (SHARED ? g_hsh + (size_t)r * I_
                             : g_hbuf + (size_t)(e * C_ + r) * I_) + j0 + tn * 8;
        #pragma unroll
        for (int j = 0; j < 8; j++) {
            float gv  = accg[i][j];
            float sig = 1.f / (1.f + expf(-gv));
            dst[j] = gv * sig * accu[i][j];
        }
    }
}

// ---------------- GEMM 2: y (+)= (h Wd^T) [* weight, scattered] -------------
template <bool SHARED>
__global__ void gemm2_kernel(const int* __restrict__ dp, const float* __restrict__ ds,
                             float* __restrict__ y) {
    extern __shared__ float sm[];
    float* As = sm;                 // [BK][BMP]
    float* Bd = sm + BK * BMP;      // [BK][BNP]

    int e     = SHARED ? 0 : blockIdx.z;
    int nrows = SHARED ? T_ : g_cnt[e];
    int r0    = blockIdx.x * BM;
    if (r0 >= nrows) return;
    int n0  = blockIdx.y * BN;
    int tid = threadIdx.x;

    int a_m = tid >> 2, a_c = tid & 3;
    int a_r = r0 + a_m;
    bool a_valid = a_r < nrows;
    const float* a_ptr = a_valid
        ? (SHARED ? g_hsh + (size_t)a_r * I_
                  : g_hbuf + (size_t)(e * C_ + a_r) * I_)
        : g_hsh;

    int bj = tid >> 1, bh = tid & 1;
    size_t wrow = ((size_t)e * H_ + (n0 + bj)) * (I_ / 8);
    size_t srow_base = (size_t)e * (I_ / GS_);

    int tn = tid & 15, tm = tid >> 4;

    float acc[4][8];
    #pragma unroll
    for (int i = 0; i < 4; i++)
        #pragma unroll
        for (int j = 0; j < 8; j++) acc[i][j] = 0.f;

    for (int kk = 0; kk < I_; kk += BK) {
        #pragma unroll
        for (int i = 0; i < 4; i++) {
            int f4 = a_c * 4 + i;
            float4 v = a_valid ? *(const float4*)(a_ptr + kk + f4 * 4)
                               : make_float4(0.f, 0.f, 0.f, 0.f);
            int k = f4 * 4;
            As[(k + 0) * BMP + a_m] = v.x;
            As[(k + 1) * BMP + a_m] = v.y;
            As[(k + 2) * BMP + a_m] = v.z;
            As[(k + 3) * BMP + a_m] = v.w;
        }
        {
            int grp = kk >> 7;
            float sv = ds[(srow_base + grp) * H_ + n0 + bj];
            int4 w = *((const int4*)(dp + wrow + (kk >> 3)) + bh);
            unsigned a4[4] = {(unsigned)w.x, (unsigned)w.y, (unsigned)w.z, (unsigned)w.w};
            int kb = bh * 32;
            #pragma unroll
            for (int q = 0; q < 4; q++) {
                #pragma unroll
                for (int t2 = 0; t2 < 8; t2++) {
                    Bd[(kb + q * 8 + t2) * BNP + bj] =
                        fp4_to_f32((a4[q] >> (4 * t2)) & 0xFu) * sv;
                }
            }
        }
        __syncthreads();

        #pragma unroll 8
        for (int k = 0; k < BK; k++) {
            float4 av = *(const float4*)&As[k * BMP + tm * 4];
            const float* bdr = &Bd[k * BNP + tn * 8];
            float4 b0 = *(const float4*)bdr;
            float4 b1 = *(const float4*)(bdr + 4);
            float am[4] = {av.x, av.y, av.z, av.w};
            float bv[8] = {b0.x, b0.y, b0.z, b0.w, b1.x, b1.y, b1.z, b1.w};
            #pragma unroll
            for (int i = 0; i < 4; i++)
                #pragma unroll
                for (int j = 0; j < 8; j++)
                    acc[i][j] = fmaf(am[i], bv[j], acc[i][j]);
        }
        __syncthreads();
    }

    if (SHARED) {
        #pragma unroll
        for (int i = 0; i < 4; i++) {
            int r = r0 + tm * 4 + i;        // always < T_
            float* dst = y + (size_t)r * H_ + n0 + tn * 8;
            #pragma unroll
            for (int j = 0; j < 8; j++) dst[j] = acc[i][j];
        }
    } else {
        #pragma unroll
        for (int i = 0; i < 4; i++) {
            int r = r0 + tm * 4 + i;
            if (r >= nrows) continue;
            int   tok = g_slotTok[e * C_ + r];
            float w   = g_slotW[e * C_ + r];
            float* dst = y + (size_t)tok * H_ + n0 + tn * 8;
            #pragma unroll
            for (int j = 0; j < 8; j++) atomicAdd(dst + j, w * acc[i][j]);
        }
    }
}

// ---------------- launch --------------------------------------------------
extern "C" void kernel_launch(void* const* d_in, const int* in_sizes, int n_in,
                              void* d_out, int out_size) {
    const float* x   = (const float*)d_in[0];
    const float* gw  = (const float*)d_in[1];
    const float* gsc = (const float*)d_in[2];
    const float* usc = (const float*)d_in[3];
    const float* dsc = (const float*)d_in[4];
    const float* sgs = (const float*)d_in[5];
    const float* sus = (const float*)d_in[6];
    const float* sds = (const float*)d_in[7];
    const int*   gpk = (const int*)d_in[8];
    const int*   upk = (const int*)d_in[9];
    const int*   dpk = (const int*)d_in[10];
    const int*   sgp = (const int*)d_in[11];
    const int*   sup = (const int*)d_in[12];
    const int*   sdp = (const int*)d_in[13];
    float* y = (float*)d_out;

    const int SM1 = (BK * BMP + 2 * BK * BNP) * 4;   // 84992 B
    const int SM2 = (BK * BMP + BK * BNP) * 4;       // 51200 B
    cudaFuncSetAttribute(gemm1_kernel<false>, cudaFuncAttributeMaxDynamicSharedMemorySize, SM1);
    cudaFuncSetAttribute(gemm1_kernel<true>,  cudaFuncAttributeMaxDynamicSharedMemorySize, SM1);
    cudaFuncSetAttribute(gemm2_kernel<false>, cudaFuncAttributeMaxDynamicSharedMemorySize, SM2);
    cudaFuncSetAttribute(gemm2_kernel<true>,  cudaFuncAttributeMaxDynamicSharedMemorySize, SM2);

    routing_kernel<<<T_ / 8, 256>>>(x, gw);
    dispatch_kernel<<<1, 64>>>();

    // stage 1: SwiGLU intermediates (experts + shared)
    gemm1_kernel<false><<<dim3(C_ / BM, I_ / BN, E_), 256, SM1>>>(x, gpk, gsc, upk, usc);
    gemm1_kernel<true><<<dim3(T_ / BM, I_ / BN, 1), 256, SM1>>>(x, sgp, sgs, sup, sus);

    // stage 2: down-proj. Shared expert writes y (initializes output),
    // experts then atomicAdd their weighted contributions on top.
    gemm2_kernel<true><<<dim3(T_ / BM, H_ / BN, 1), 256, SM2>>>(sdp, sds, y);
    gemm2_kernel<false><<<dim3(C_ / BM, H_ / BN, E_), 256, SM2>>>(dpk, dsc, y);
}

// round 3
// speedup vs baseline: 4.5500x; 4.5500x over previous
#include <cuda_runtime.h>
#include <cuda_fp16.h>
#include <math.h>

#define E_   64
#define KTOP 4
#define H_   2048
#define I_   1536
#define GS_  128
#define T_   1024
#define C_   128

// Does this device pass support tcgen05 (arch-accelerated sm_100a/sm_103a)?
#if defined(__CUDA_ARCH__) && !defined(__CUDA_ARCH_FEAT_SM103_ALL) && !defined(__CUDA_ARCH_FEAT_SM100_ALL)
#define TC_OK 0
#else
#define TC_OK 1
#endif

// ---------------------------------------------------------------------------
// common helpers
// ---------------------------------------------------------------------------
__device__ __forceinline__ unsigned smem_u32(const void* p) {
    unsigned a;
    asm("{ .reg .u64 t; cvta.to.shared.u64 t, %1; cvt.u32.u64 %0, t; }" : "=r"(a) : "l"(p));
    return a;
}
__device__ __forceinline__ unsigned h2u(__half2 h) {
    return *reinterpret_cast<unsigned*>(&h);
}
__device__ __forceinline__ void st_sw(char* base, int off, uint4 v) {
    *reinterpret_cast<uint4*>(base + (off ^ ((off >> 3) & 0x70))) = v;
}
__device__ __forceinline__ unsigned swadr(unsigned base, int row, int col) {
    unsigned off = (unsigned)(row * 128 + col);
    return base + (off ^ ((off >> 3) & 0x70));
}
// FP4 E2M1 -> f32 (exact)
__device__ __forceinline__ float fp4_to_f32(unsigned v) {
    unsigned s = (v & 8u) << 28;
    unsigned e = (v >> 1) & 3u;
    unsigned m = v & 1u;
    unsigned bits = e ? (((126u + e) << 23) | (m << 22))
                      : (m ? 0x3F000000u : 0u);
    return __uint_as_float(bits | s);
}
// one packed word (8 nibbles) * scale -> 8 fp16
__device__ __forceinline__ uint4 dec8(unsigned w, float s) {
    unsigned o[4];
    #pragma unroll
    for (int p = 0; p < 4; p++) {
        float f0 = fp4_to_f32((w >> (8 * p)) & 0xFu) * s;
        float f1 = fp4_to_f32((w >> (8 * p + 4)) & 0xFu) * s;
        o[p] = h2u(__float22half2_rn(make_float2(f0, f1)));
    }
    return make_uint4(o[0], o[1], o[2], o[3]);
}
// stage 64 fp32 -> fp16 SW128 (per thread: 32 halves at row lrow, half lh)
__device__ __forceinline__ void stage_A_f32(char* At, const float* arow, int kk,
                                            int bo, int lh) {
    #pragma unroll
    for (int q = 0; q < 4; q++) {
        const float* p = arow + kk + lh * 32 + q * 8;
        float4 fa = *(const float4*)p;
        float4 fb = *(const float4*)(p + 4);
        uint4 v;
        v.x = h2u(__float22half2_rn(make_float2(fa.x, fa.y)));
        v.y = h2u(__float22half2_rn(make_float2(fa.z, fa.w)));
        v.z = h2u(__float22half2_rn(make_float2(fb.x, fb.y)));
        v.w = h2u(__float22half2_rn(make_float2(fb.z, fb.w)));
        st_sw(At, bo + q * 16, v);
    }
}
__device__ __forceinline__ void stage_A_f16(char* At, const __half* arow, int kk,
                                            int bo, int lh) {
    #pragma unroll
    for (int q = 0; q < 4; q++) {
        uint4 v = *reinterpret_cast<const uint4*>(arow + kk + lh * 32 + q * 8);
        st_sw(At, bo + q * 16, v);
    }
}
__device__ __forceinline__ void stage_B(char* Bt, const int* wp, float s, int bo) {
    int4 w = *(const int4*)wp;
    st_sw(Bt, bo + 0,  dec8((unsigned)w.x, s));
    st_sw(Bt, bo + 16, dec8((unsigned)w.y, s));
    st_sw(Bt, bo + 32, dec8((unsigned)w.z, s));
    st_sw(Bt, bo + 48, dec8((unsigned)w.w, s));
}

// ---------------------------------------------------------------------------
// scratch
// ---------------------------------------------------------------------------
__device__ int    g_ti[T_ * KTOP];
__device__ float  g_tw[T_ * KTOP];
__device__ int    g_cnt[E_];
__device__ int    g_slotTok[E_ * C_];
__device__ float  g_slotW[E_ * C_];
__device__ __half g_hbuf[(size_t)E_ * C_ * I_];
__device__ __half g_hsh[(size_t)T_ * I_];

// ---------------------------------------------------------------------------
// routing + dispatch
// ---------------------------------------------------------------------------
__global__ void routing_kernel(const float* __restrict__ x,
                               const float* __restrict__ gw) {
    __shared__ float lg[8][E_];
    int tid  = threadIdx.x;
    int tok0 = blockIdx.x * 8;
    #pragma unroll
    for (int p = 0; p < 2; p++) {
        int pair = tid + p * 256;
        int tk = pair >> 6, e = pair & 63;
        const float* xr = x  + (size_t)(tok0 + tk) * H_;
        const float* wr = gw + (size_t)e * H_;
        float acc = 0.f;
        for (int h = 0; h < H_; h += 4) {
            float4 a = *(const float4*)(xr + h);
            float4 b = *(const float4*)(wr + h);
            acc += a.x * b.x + a.y * b.y + a.z * b.z + a.w * b.w;
        }
        lg[tk][e] = acc;
    }
    __syncthreads();
    if (tid < 8) {
        int t = tok0 + tid;
        unsigned long long used = 0ull;
        float v[KTOP]; int id[KTOP];
        #pragma unroll
        for (int k = 0; k < KTOP; k++) {
            float best = -INFINITY; int bi = 0;
            for (int e = 0; e < E_; e++)
                if (!((used >> e) & 1ull) && lg[tid][e] > best) { best = lg[tid][e]; bi = e; }
            v[k] = best; id[k] = bi; used |= 1ull << bi;
        }
        float mx = v[0], w[KTOP], sum = 0.f;
        #pragma unroll
        for (int k = 0; k < KTOP; k++) { w[k] = expf(v[k] - mx); sum += w[k]; }
        #pragma unroll
        for (int k = 0; k < KTOP; k++) {
            g_ti[t * KTOP + k] = id[k];
            g_tw[t * KTOP + k] = w[k] / sum;
        }
    }
}

__global__ void dispatch_kernel() {
    __shared__ int sti[T_ * KTOP];
    int tid = threadIdx.x;
    for (int i = tid; i < T_ * KTOP; i += blockDim.x) sti[i] = g_ti[i];
    __syncthreads();
    int wid = tid >> 5, lane = tid & 31;
    int e = blockIdx.x * (blockDim.x >> 5) + wid;
    if (e < E_) {
        int cnt = 0;
        for (int base = 0; base < T_ * KTOP; base += 32) {
            int a = base + lane;
            bool m = (sti[a] == e);
            unsigned msk = __ballot_sync(0xffffffffu, m);
            if (m) {
                int c = cnt + __popc(msk & ((1u << lane) - 1u));
                if (c < C_) {
                    g_slotTok[e * C_ + c] = a >> 2;
                    g_slotW[e * C_ + c]   = g_tw[a];
                }
            }
            cnt += __popc(msk);
        }
        if (lane == 0) g_cnt[e] = cnt < C_ ? cnt : C_;
    }
}

// SMEM layout (shared by both paths)
#define OFF_A  1024
#define OFF_BG 33792
#define OFF_BU 66560
#define SM1    99328
#define SM2    66560
#define STG    16384

#if TC_OK
// ===========================================================================
// tcgen05 path (sm_103a / sm_100a)
// ===========================================================================
#define TC_ALLOC(sm, n)  asm volatile("tcgen05.alloc.cta_group::1.sync.aligned.shared::cta.b32 [%0], %1;" :: "r"(sm), "r"(n) : "memory")
#define TC_DEALLOC(tb,n) asm volatile("tcgen05.dealloc.cta_group::1.sync.aligned.b32 %0, %1;" :: "r"(tb), "r"(n))
#define TC_RELINQ()      asm volatile("tcgen05.relinquish_alloc_permit.cta_group::1.sync.aligned;")
#define TC_COMMIT(bar)   asm volatile("tcgen05.commit.cta_group::1.mbarrier::arrive::one.shared::cluster.b64 [%0];" :: "r"(bar) : "memory")
#define TC_FENCE_AFTER()  asm volatile("tcgen05.fence::after_thread_sync;" ::: "memory")
#define TC_FENCE_BEFORE() asm volatile("tcgen05.fence::before_thread_sync;" ::: "memory")
#define TC_WAIT_LD()      asm volatile("tcgen05.wait::ld.sync.aligned;" ::: "memory")
#define FENCE_ASYNC()     asm volatile("fence.proxy.async.shared::cta;" ::: "memory")
#define MBAR_INIT(a, c)  asm volatile("mbarrier.init.shared.b64 [%0], %1;" :: "r"(a), "r"(c) : "memory")
#define MBAR_INVAL(a)    asm volatile("mbarrier.inval.shared.b64 [%0];" :: "r"(a) : "memory")

#define MBAR_WAIT(addr, par) do {                                              \
    unsigned _m = (unsigned)(addr), _p = (unsigned)(par), _d;                  \
    asm volatile("{\n\t.reg .pred p;\n\t"                                      \
        "mbarrier.try_wait.parity.acquire.cta.shared::cta.b64 p, [%1], %2;\n\t"\
        "selp.b32 %0,1,0,p;\n\t}" : "=r"(_d) : "r"(_m), "r"(_p) : "memory");   \
    if (!_d) {                                                                 \
        asm volatile("{\n\t.reg .pred P1;\n\t"                                 \
        "WL_%=:\n\t"                                                           \
        "mbarrier.try_wait.parity.acquire.cta.shared::cta.b64 P1, [%0], %1, 0x989680;\n\t" \
        "@P1 bra.uni WD_%=;\n\t"                                               \
        "bra.uni WL_%=;\n\t"                                                   \
        "WD_%=:\n\t}" :: "r"(_m), "r"(_p) : "memory");                         \
    }                                                                          \
} while (0)

#define TC_LD32(r, ta) \
    asm volatile( \
        "tcgen05.ld.sync.aligned.32x32b.x32.b32 " \
        "{%0, %1, %2, %3, %4, %5, %6, %7, " \
        " %8, %9, %10, %11, %12, %13, %14, %15, " \
        " %16, %17, %18, %19, %20, %21, %22, %23, " \
        " %24, %25, %26, %27, %28, %29, %30, %31}, [%32];" \
        : "=r"((r)[0]),  "=r"((r)[1]),  "=r"((r)[2]),  "=r"((r)[3]), \
          "=r"((r)[4]),  "=r"((r)[5]),  "=r"((r)[6]),  "=r"((r)[7]), \
          "=r"((r)[8]),  "=r"((r)[9]),  "=r"((r)[10]), "=r"((r)[11]), \
          "=r"((r)[12]), "=r"((r)[13]), "=r"((r)[14]), "=r"((r)[15]), \
          "=r"((r)[16]), "=r"((r)[17]), "=r"((r)[18]), "=r"((r)[19]), \
          "=r"((r)[20]), "=r"((r)[21]), "=r"((r)[22]), "=r"((r)[23]), \
          "=r"((r)[24]), "=r"((r)[25]), "=r"((r)[26]), "=r"((r)[27]), \
          "=r"((r)[28]), "=r"((r)[29]), "=r"((r)[30]), "=r"((r)[31]) \
        : "r"(ta))

// idesc: dtype=F32, atype=btype=FP16 (=0), N=128, M=128
#define IDESC_F16 ((1u << 4) | (16u << 17) | (8u << 24))

__device__ __forceinline__ void mma_f16_ss(unsigned d, unsigned long long a,
                                           unsigned long long b, unsigned en) {
    asm volatile("{\n\t.reg .pred p;\n\tsetp.ne.u32 p, %4, 0;\n\t"
        "tcgen05.mma.cta_group::1.kind::f16 [%0], %1, %2, %3, {%5,%5,%5,%5}, p;\n\t}"
        :: "r"(d), "l"(a), "l"(b), "r"(IDESC_F16), "r"(en), "r"(0u) : "memory");
}
__device__ __forceinline__ unsigned long long make_desc(unsigned addr) {
    return ((unsigned long long)2 << 61) | ((unsigned long long)1 << 46)
         | ((unsigned long long)64 << 32) | ((unsigned long long)1 << 16)
         | ((addr >> 4) & 0x3FFFu);
}

template <bool EXP>
__global__ __launch_bounds__(256) void mma_gemm1(
    const float* __restrict__ x,
    const int* __restrict__ gp, const float* __restrict__ gsc,
    const int* __restrict__ upk, const float* __restrict__ usc) {
    constexpr int NC = H_ / 64;
    extern __shared__ char smem[];
    const int tid = threadIdx.x, wid = tid >> 5, lid = tid & 31;
    const int j0 = blockIdx.x * 128;
    int e, m0, nrows;
    if (EXP) { e = blockIdx.y; m0 = 0; nrows = g_cnt[e]; if (nrows == 0) return; }
    else     { e = 0; m0 = blockIdx.y * 128; nrows = 128; }

    unsigned sb = smem_u32(smem);
    if (wid == 0) TC_ALLOC(sb, 256);
    if (tid == 0) { MBAR_INIT(sb + 8, 1); MBAR_INIT(sb + 16, 1); }
    __syncthreads();
    unsigned tb;
    asm("ld.shared.b32 %0, [%1];" : "=r"(tb) : "r"(sb));

    const int lrow = tid >> 1, lh = tid & 1;
    const float* arow = nullptr;
    if (EXP) { if (lrow < nrows) arow = x + (size_t)g_slotTok[e * C_ + lrow] * H_; }
    else       arow = x + (size_t)(m0 + lrow) * H_;

    const int* gpr = gp  + ((size_t)e * I_ + j0 + lrow) * (H_ / 8) + lh * 4;
    const int* upr = upk + ((size_t)e * I_ + j0 + lrow) * (H_ / 8) + lh * 4;
    const float* gsp = gsc + (size_t)e * (H_ / GS_) * I_ + j0 + lrow;
    const float* usp = usc + (size_t)e * (H_ / GS_) * I_ + j0 + lrow;
    const int bo = lrow * 128 + lh * 64;

    int ph0 = 0, ph1 = 0;
    for (int c = 0; c < NC; c++) {
        int s = c & 1;
        if (c >= 2) {
            if (s == 0) { MBAR_WAIT(sb + 8,  ph0); ph0 ^= 1; }
            else        { MBAR_WAIT(sb + 16, ph1); ph1 ^= 1; }
        }
        int kk = c * 64;
        char* At = smem + OFF_A  + s * STG;
        char* Bg = smem + OFF_BG + s * STG;
        char* Bu = smem + OFF_BU + s * STG;
        if (arow) stage_A_f32(At, arow, kk, bo, lh);
        stage_B(Bg, gpr + (kk >> 3), gsp[(size_t)(kk >> 7) * I_], bo);
        stage_B(Bu, upr + (kk >> 3), usp[(size_t)(kk >> 7) * I_], bo);
        FENCE_ASYNC();
        __syncthreads();
        if (tid == 0) {
            unsigned long long ad = make_desc(sb + OFF_A  + s * STG);
            unsigned long long gd = make_desc(sb + OFF_BG + s * STG);
            unsigned long long ud = make_desc(sb + OFF_BU + s * STG);
            #pragma unroll
            for (int ks = 0; ks < 4; ks++) {
                unsigned en = (c > 0 || ks > 0) ? 1u : 0u;
                mma_f16_ss(tb,        ad + ks * 2, gd + ks * 2, en);
                mma_f16_ss(tb + 128,  ad + ks * 2, ud + ks * 2, en);
            }
            TC_COMMIT(sb + 8 + 8 * s);
        }
    }
    MBAR_WAIT(sb + 16, ph1);
    TC_FENCE_AFTER();

    const int w4 = wid & 3, hf = wid >> 2;
    const int r = w4 * 32 + lid;
    bool valid = EXP ? (r < nrows) : true;
    __half* drow = EXP ? (g_hbuf + ((size_t)e * C_ + r) * I_)
                       : (g_hsh  + (size_t)(m0 + r) * I_);
    #pragma unroll
    for (int b = 0; b < 2; b++) {
        int cb = hf * 64 + b * 32;
        unsigned gr[32], ur[32];
        TC_LD32(gr, tb + cb);
        TC_LD32(ur, tb + 128 + cb);
        TC_WAIT_LD();
        if (valid) {
            #pragma unroll
            for (int q = 0; q < 4; q++) {
                float v[8];
                #pragma unroll
                for (int t = 0; t < 8; t++) {
                    int j = q * 8 + t;
                    float gv = __uint_as_float(gr[j]);
                    float uv = __uint_as_float(ur[j]);
                    v[t] = gv / (1.f + expf(-gv)) * uv;
                }
                uint4 o;
                o.x = h2u(__float22half2_rn(make_float2(v[0], v[1])));
                o.y = h2u(__float22half2_rn(make_float2(v[2], v[3])));
                o.z = h2u(__float22half2_rn(make_float2(v[4], v[5])));
                o.w = h2u(__float22half2_rn(make_float2(v[6], v[7])));
                *reinterpret_cast<uint4*>(drow + j0 + cb + q * 8) = o;
            }
        }
    }
    TC_FENCE_BEFORE();
    __syncthreads();
    if (tid == 0) { MBAR_INVAL(sb + 8); MBAR_INVAL(sb + 16); }
    __syncthreads();
    if (wid == 0) { TC_RELINQ(); TC_DEALLOC(tb, 256); }
}

template <bool EXP>
__global__ __launch_bounds__(256) void mma_gemm2(
    const int* __restrict__ dp, const float* __restrict__ dsc,
    float* __restrict__ y) {
    constexpr int NC = I_ / 64;   // 24
    extern __shared__ char smem[];
    const int tid = threadIdx.x, wid = tid >> 5, lid = tid & 31;
    const int n0 = blockIdx.x * 128;
    int e, m0, nrows;
    if (EXP) { e = blockIdx.y; m0 = 0; nrows = g_cnt[e]; if (nrows == 0) return; }
    else     { e = 0; m0 = blockIdx.y * 128; nrows = 128; }

    unsigned sb = smem_u32(smem);
    if (wid == 0) TC_ALLOC(sb, 128);
    if (tid == 0) { MBAR_INIT(sb + 8, 1); MBAR_INIT(sb + 16, 1); }
    __syncthreads();
    unsigned tb;
    asm("ld.shared.b32 %0, [%1];" : "=r"(tb) : "r"(sb));

    const int lrow = tid >> 1, lh = tid & 1;
    const __half* arow = EXP ? (g_hbuf + ((size_t)e * C_ + lrow) * I_)
                             : (g_hsh  + (size_t)(m0 + lrow) * I_);
    const int* dpr = dp + ((size_t)e * H_ + n0 + lrow) * (I_ / 8) + lh * 4;
    const float* dsp = dsc + (size_t)e * (I_ / GS_) * H_ + n0 + lrow;
    const int bo = lrow * 128 + lh * 64;

    int ph0 = 0, ph1 = 0;
    for (int c = 0; c < NC; c++) {
        int s = c & 1;
        if (c >= 2) {
            if (s == 0) { MBAR_WAIT(sb + 8,  ph0); ph0 ^= 1; }
            else        { MBAR_WAIT(sb + 16, ph1); ph1 ^= 1; }
        }
        int kk = c * 64;
        char* At = smem + OFF_A  + s * STG;
        char* Bt = smem + OFF_BG + s * STG;
        stage_A_f16(At, arow, kk, bo, lh);
        stage_B(Bt, dpr + (kk >> 3), dsp[(size_t)(kk >> 7) * H_], bo);
        FENCE_ASYNC();
        __syncthreads();
        if (tid == 0) {
            unsigned long long ad = make_desc(sb + OFF_A  + s * STG);
            unsigned long long bd = make_desc(sb + OFF_BG + s * STG);
            #pragma unroll
            for (int ks = 0; ks < 4; ks++) {
                unsigned en = (c > 0 || ks > 0) ? 1u : 0u;
                mma_f16_ss(tb, ad + ks * 2, bd + ks * 2, en);
            }
            TC_COMMIT(sb + 8 + 8 * s);
        }
    }
    MBAR_WAIT(sb + 16, ph1);
    TC_FENCE_AFTER();

    const int w4 = wid & 3, hf = wid >> 2;
    const int r = w4 * 32 + lid;
    bool valid = EXP ? (r < nrows) : true;
    int   tok = 0; float wgt = 1.f;
    if (EXP && valid) { tok = g_slotTok[e * C_ + r]; wgt = g_slotW[e * C_ + r]; }
    #pragma unroll
    for (int b = 0; b < 2; b++) {
        int cb = hf * 64 + b * 32;
        unsigned dr[32];
        TC_LD32(dr, tb + cb);
        TC_WAIT_LD();
        if (valid) {
            if (EXP) {
                float* dst = y + (size_t)tok * H_ + n0 + cb;
                #pragma unroll
                for (int j = 0; j < 32; j++)
                    atomicAdd(dst + j, wgt * __uint_as_float(dr[j]));
            } else {
                float* dst = y + (size_t)(m0 + r) * H_ + n0 + cb;
                #pragma unroll
                for (int j = 0; j < 32; j++)
                    dst[j] = __uint_as_float(dr[j]);
            }
        }
    }
    TC_FENCE_BEFORE();
    __syncthreads();
    if (tid == 0) { MBAR_INVAL(sb + 8); MBAR_INVAL(sb + 16); }
    __syncthreads();
    if (wid == 0) { TC_RELINQ(); TC_DEALLOC(tb, 128); }
}

#else  // !TC_OK
// ===========================================================================
// fallback path: mma.sync.m16n8k16 (HMMA) — compiles for plain sm_103
// ===========================================================================
__device__ __forceinline__ void ldm_x4(unsigned r[4], unsigned a) {
    asm volatile("ldmatrix.sync.aligned.m8n8.x4.shared.b16 {%0,%1,%2,%3}, [%4];"
                 : "=r"(r[0]), "=r"(r[1]), "=r"(r[2]), "=r"(r[3]) : "r"(a));
}
__device__ __forceinline__ void ldm_x2(unsigned r[2], unsigned a) {
    asm volatile("ldmatrix.sync.aligned.m8n8.x2.shared.b16 {%0,%1}, [%2];"
                 : "=r"(r[0]), "=r"(r[1]) : "r"(a));
}
__device__ __forceinline__ void mma16816(float* d, const unsigned* a, const unsigned* b) {
    asm volatile("mma.sync.aligned.m16n8k16.row.col.f32.f16.f16.f32 "
        "{%0,%1,%2,%3}, {%4,%5,%6,%7}, {%8,%9}, {%0,%1,%2,%3};"
        : "+f"(d[0]), "+f"(d[1]), "+f"(d[2]), "+f"(d[3])
        : "r"(a[0]), "r"(a[1]), "r"(a[2]), "r"(a[3]), "r"(b[0]), "r"(b[1]));
}

template <bool EXP>
__global__ __launch_bounds__(256) void mma_gemm1(
    const float* __restrict__ x,
    const int* __restrict__ gp, const float* __restrict__ gsc,
    const int* __restrict__ upk, const float* __restrict__ usc) {
    constexpr int NC = H_ / 64;
    extern __shared__ char smem[];
    const int tid = threadIdx.x, wid = tid >> 5, lane = tid & 31;
    const int j0 = blockIdx.x * 128;
    int e, m0, nrows;
    if (EXP) { e = blockIdx.y; m0 = 0; nrows = g_cnt[e]; if (nrows == 0) return; }
    else     { e = 0; m0 = blockIdx.y * 128; nrows = 128; }

    unsigned sb = smem_u32(smem);
    const unsigned Ab = sb + OFF_A, Bgb = sb + OFF_BG, Bub = sb + OFF_BU;

    const int lrow = tid >> 1, lh = tid & 1;
    const float* arow = nullptr;
    if (EXP) { if (lrow < nrows) arow = x + (size_t)g_slotTok[e * C_ + lrow] * H_; }
    else       arow = x + (size_t)(m0 + lrow) * H_;
    const int* gpr = gp  + ((size_t)e * I_ + j0 + lrow) * (H_ / 8) + lh * 4;
    const int* upr = upk + ((size_t)e * I_ + j0 + lrow) * (H_ / 8) + lh * 4;
    const float* gsp = gsc + (size_t)e * (H_ / GS_) * I_ + j0 + lrow;
    const float* usp = usc + (size_t)e * (H_ / GS_) * I_ + j0 + lrow;
    const int bo = lrow * 128 + lh * 64;

    const int wm = wid >> 2, wn = wid & 3;          // warp tile 64 x 32

    float ag[4][4][4], au[4][4][4];
    #pragma unroll
    for (int i = 0; i < 4; i++)
        #pragma unroll
        for (int j = 0; j < 4; j++)
            #pragma unroll
            for (int q = 0; q < 4; q++) { ag[i][j][q] = 0.f; au[i][j][q] = 0.f; }

    for (int c = 0; c < NC; c++) {
        int kk = c * 64;
        if (arow) stage_A_f32(smem + OFF_A, arow, kk, bo, lh);
        stage_B(smem + OFF_BG, gpr + (kk >> 3), gsp[(size_t)(kk >> 7) * I_], bo);
        stage_B(smem + OFF_BU, upr + (kk >> 3), usp[(size_t)(kk >> 7) * I_], bo);
        __syncthreads();

        #pragma unroll
        for (int ks = 0; ks < 4; ks++) {
            unsigned af[4][4];
            #pragma unroll
            for (int mt = 0; mt < 4; mt++)
                ldm_x4(af[mt], swadr(Ab, wm * 64 + mt * 16 + (lane & 15),
                                     ks * 32 + (lane >> 4) * 16));
            #pragma unroll
            for (int nt = 0; nt < 4; nt++) {
                int brow = wn * 32 + nt * 8 + (lane & 7);
                int bcol = ks * 32 + ((lane >> 3) & 1) * 16;
                unsigned bg[2], bu[2];
                ldm_x2(bg, swadr(Bgb, brow, bcol));
                ldm_x2(bu, swadr(Bub, brow, bcol));
                #pragma unroll
                for (int mt = 0; mt < 4; mt++) {
                    mma16816(ag[mt][nt], af[mt], bg);
                    mma16816(au[mt][nt], af[mt], bu);
                }
            }
        }
        __syncthreads();
    }

    // fused SwiGLU epilogue
    const int g = lane >> 2, cq = lane & 3;
    #pragma unroll
    for (int mt = 0; mt < 4; mt++) {
        #pragma unroll
        for (int nt = 0; nt < 4; nt++) {
            int nn = j0 + wn * 32 + nt * 8 + cq * 2;
            #pragma unroll
            for (int hrow = 0; hrow < 2; hrow++) {
                int r = wm * 64 + mt * 16 + g + hrow * 8;
                if (EXP && r >= nrows) continue;
                float g0 = ag[mt][nt][hrow * 2], g1 = ag[mt][nt][hrow * 2 + 1];
                float u0 = au[mt][nt][hrow * 2], u1 = au[mt][nt][hrow * 2 + 1];
                float v0 = g0 / (1.f + expf(-g0)) * u0;
                float v1 = g1 / (1.f + expf(-g1)) * u1;
                __half* dst = (EXP ? g_hbuf + ((size_t)e * C_ + r) * I_
                                   : g_hsh + (size_t)(m0 + r) * I_) + nn;
                *reinterpret_cast<__half2*>(dst) =
                    __float22half2_rn(make_float2(v0, v1));
            }
        }
    }
}

template <bool EXP>
__global__ __launch_bounds__(256) void mma_gemm2(
    const int* __restrict__ dp, const float* __restrict__ dsc,
    float* __restrict__ y) {
    constexpr int NC = I_ / 64;
    extern __shared__ char smem[];
    const int tid = threadIdx.x, wid = tid >> 5, lane = tid & 31;
    const int n0 = blockIdx.x * 128;
    int e, m0, nrows;
    if (EXP) { e = blockIdx.y; m0 = 0; nrows = g_cnt[e]; if (nrows == 0) return; }
    else     { e = 0; m0 = blockIdx.y * 128; nrows = 128; }

    unsigned sb = smem_u32(smem);
    const unsigned Ab = sb + OFF_A, Bb = sb + OFF_BG;

    const int lrow = tid >> 1, lh = tid & 1;
    const __half* arow = EXP ? (g_hbuf + ((size_t)e * C_ + lrow) * I_)
                             : (g_hsh  + (size_t)(m0 + lrow) * I_);
    const int* dpr = dp + ((size_t)e * H_ + n0 + lrow) * (I_ / 8) + lh * 4;
    const float* dsp = dsc + (size_t)e * (I_ / GS_) * H_ + n0 + lrow;
    const int bo = lrow * 128 + lh * 64;

    const int wm = wid >> 2, wn = wid & 3;

    float acc[4][4][4];
    #pragma unroll
    for (int i = 0; i < 4; i++)
        #pragma unroll
        for (int j = 0; j < 4; j++)
            #pragma unroll
            for (int q = 0; q < 4; q++) acc[i][j][q] = 0.f;

    for (int c = 0; c < NC; c++) {
        int kk = c * 64;
        stage_A_f16(smem + OFF_A, arow, kk, bo, lh);
        stage_B(smem + OFF_BG, dpr + (kk >> 3), dsp[(size_t)(kk >> 7) * H_], bo);
        __syncthreads();

        #pragma unroll
        for (int ks = 0; ks < 4; ks++) {
            unsigned af[4][4];
            #pragma unroll
            for (int mt = 0; mt < 4; mt++)
                ldm_x4(af[mt], swadr(Ab, wm * 64 + mt * 16 + (lane & 15),
                                     ks * 32 + (lane >> 4) * 16));
            #pragma unroll
            for (int nt = 0; nt < 4; nt++) {
                int brow = wn * 32 + nt * 8 + (lane & 7);
                int bcol = ks * 32 + ((lane >> 3) & 1) * 16;
                unsigned bf[2];
                ldm_x2(bf, swadr(Bb, brow, bcol));
                #pragma unroll
                for (int mt = 0; mt < 4; mt++)
                    mma16816(acc[mt][nt], af[mt], bf);
            }
        }
        __syncthreads();
    }

    const int g = lane >> 2, cq = lane & 3;
    #pragma unroll
    for (int mt = 0; mt < 4; mt++) {
        #pragma unroll
        for (int hrow = 0; hrow < 2; hrow++) {
            int r = wm * 64 + mt * 16 + g + hrow * 8;
            if (EXP && r >= nrows) continue;
            int tok = 0; float wgt = 1.f;
            if (EXP) { tok = g_slotTok[e * C_ + r]; wgt = g_slotW[e * C_ + r]; }
            #pragma unroll
            for (int nt = 0; nt < 4; nt++) {
                int nn = n0 + wn * 32 + nt * 8 + cq * 2;
                float v0 = acc[mt][nt][hrow * 2], v1 = acc[mt][nt][hrow * 2 + 1];
                if (EXP) {
                    float* dst = y + (size_t)tok * H_ + nn;
                    atomicAdd(dst,     wgt * v0);
                    atomicAdd(dst + 1, wgt * v1);
                } else {
                    float* dst = y + (size_t)(m0 + r) * H_ + nn;
                    dst[0] = v0; dst[1] = v1;
                }
            }
        }
    }
}
#endif  // TC_OK

// ---------------------------------------------------------------------------
// launch
// ---------------------------------------------------------------------------
extern "C" void kernel_launch(void* const* d_in, const int* in_sizes, int n_in,
                              void* d_out, int out_size) {
    const float* x   = (const float*)d_in[0];
    const float* gw  = (const float*)d_in[1];
    const float* gsc = (const float*)d_in[2];
    const float* usc = (const float*)d_in[3];
    const float* dsc = (const float*)d_in[4];
    const float* sgs = (const float*)d_in[5];
    const float* sus = (const float*)d_in[6];
    const float* sds = (const float*)d_in[7];
    const int*   gpk = (const int*)d_in[8];
    const int*   upk = (const int*)d_in[9];
    const int*   dpk = (const int*)d_in[10];
    const int*   sgp = (const int*)d_in[11];
    const int*   sup = (const int*)d_in[12];
    const int*   sdp = (const int*)d_in[13];
    float* y = (float*)d_out;

    cudaFuncSetAttribute(mma_gemm1<true>,  cudaFuncAttributeMaxDynamicSharedMemorySize, SM1);
    cudaFuncSetAttribute(mma_gemm1<false>, cudaFuncAttributeMaxDynamicSharedMemorySize, SM1);
    cudaFuncSetAttribute(mma_gemm2<true>,  cudaFuncAttributeMaxDynamicSharedMemorySize, SM2);
    cudaFuncSetAttribute(mma_gemm2<false>, cudaFuncAttributeMaxDynamicSharedMemorySize, SM2);

    routing_kernel<<<T_ / 8, 256>>>(x, gw);
    dispatch_kernel<<<2, 1024>>>();

    // stage 1: SwiGLU intermediates
    mma_gemm1<true><<<dim3(I_ / 128, E_), 256, SM1>>>(x, gpk, gsc, upk, usc);
    mma_gemm1<false><<<dim3(I_ / 128, T_ / 128), 256, SM1>>>(x, sgp, sgs, sup, sus);

    // stage 2: shared expert writes y first (initializes output), experts add
    mma_gemm2<false><<<dim3(H_ / 128, T_ / 128), 256, SM2>>>(sdp, sds, y);
    mma_gemm2<true><<<dim3(H_ / 128, E_), 256, SM2>>>(dpk, dsc, y);
}

// round 4
// speedup vs baseline: 6.0634x; 1.3326x over previous
#include <cuda_runtime.h>
#include <cuda_fp16.h>
#include <math.h>

#define E_   64
#define KTOP 4
#define H_   2048
#define I_   1536
#define GS_  128
#define T_   1024
#define C_   128

// Does this device pass support tcgen05 (arch-accelerated sm_100a/sm_103a)?
#if defined(__CUDA_ARCH__) && !defined(__CUDA_ARCH_FEAT_SM103_ALL) && !defined(__CUDA_ARCH_FEAT_SM100_ALL)
#define TC_OK 0
#else
#define TC_OK 1
#endif

// ---------------------------------------------------------------------------
// common helpers
// ---------------------------------------------------------------------------
__device__ __forceinline__ unsigned smem_u32(const void* p) {
    unsigned a;
    asm("{ .reg .u64 t; cvta.to.shared.u64 t, %1; cvt.u32.u64 %0, t; }" : "=r"(a) : "l"(p));
    return a;
}
__device__ __forceinline__ unsigned h2u(__half2 h) {
    return *reinterpret_cast<unsigned*>(&h);
}
__device__ __forceinline__ void st_sw(char* base, int off, uint4 v) {
    *reinterpret_cast<uint4*>(base + (off ^ ((off >> 3) & 0x70))) = v;
}
__device__ __forceinline__ unsigned swadr(unsigned base, int row, int col) {
    unsigned off = (unsigned)(row * 128 + col);
    return base + (off ^ ((off >> 3) & 0x70));
}
__device__ __forceinline__ unsigned pack_sc(float s) {
    return h2u(__float2half2_rn(s));
}

// FP4 E2M1 x8 -> 8 fp16 via PRMT tables; sc2 = half2(scale, scale)
// fp16 high bytes of magnitudes {0,.5,1,1.5} and {2,3,4,6}
__device__ __forceinline__ uint4 dec8p(unsigned w, unsigned sc2) {
    const unsigned tLo = 0x3E3C3800u, tHi = 0x46444240u;
    unsigned m0, m1;
    asm("prmt.b32 %0,%1,%2,%3;" : "=r"(m0) : "r"(tLo), "r"(tHi), "r"(w & 0x7777u));
    asm("prmt.b32 %0,%1,%2,%3;" : "=r"(m1) : "r"(tLo), "r"(tHi), "r"((w >> 16) & 0x7777u));
    unsigned q4 = (w << 4) & 0x80808080u;   // byte p bit7 = sign(n_{2p})
    unsigned q0 = w & 0x80808080u;          // byte p bit7 = sign(n_{2p+1})
    unsigned r[4];
    #pragma unroll
    for (int p = 0; p < 4; p++) {
        unsigned mag  = (p < 2) ? m0 : m1;
        unsigned mctl = (p & 1) ? 0x3424u : 0x1404u;
        unsigned me, se;
        asm("prmt.b32 %0,%1,%2,%3;" : "=r"(me) : "r"(mag), "r"(0u), "r"(mctl));
        unsigned sctl = 0x4000u + (unsigned)p * 0x1010u;   // c3=4+p, c1=p
        asm("prmt.b32 %0,%1,%2,%3;" : "=r"(se) : "r"(q4), "r"(q0), "r"(sctl));
        unsigned v = me | (se & 0x80008000u);
        asm("mul.rn.f16x2 %0,%1,%2;" : "=r"(r[p]) : "r"(v), "r"(sc2));
    }
    return make_uint4(r[0], r[1], r[2], r[3]);
}

// decode one int4 (4 words = 32 nibbles) into SW128 tile at row offset bo
__device__ __forceinline__ void stage_B(char* Bt, int4 w, unsigned sc2, int bo) {
    st_sw(Bt, bo + 0,  dec8p((unsigned)w.x, sc2));
    st_sw(Bt, bo + 16, dec8p((unsigned)w.y, sc2));
    st_sw(Bt, bo + 32, dec8p((unsigned)w.z, sc2));
    st_sw(Bt, bo + 48, dec8p((unsigned)w.w, sc2));
}

// stage 32 fp32 -> fp16 SW128 (row lrow, half lh)
__device__ __forceinline__ void stage_A_f32(char* At, const float* arow, int kk,
                                            int bo, int lh) {
    #pragma unroll
    for (int q = 0; q < 4; q++) {
        const float* p = arow + kk + lh * 32 + q * 8;
        float4 fa = *(const float4*)p;
        float4 fb = *(const float4*)(p + 4);
        uint4 v;
        v.x = h2u(__float22half2_rn(make_float2(fa.x, fa.y)));
        v.y = h2u(__float22half2_rn(make_float2(fa.z, fa.w)));
        v.z = h2u(__float22half2_rn(make_float2(fb.x, fb.y)));
        v.w = h2u(__float22half2_rn(make_float2(fb.z, fb.w)));
        st_sw(At, bo + q * 16, v);
    }
}
__device__ __forceinline__ void stage_A_f16(char* At, const __half* arow, int kk,
                                            int bo, int lh) {
    #pragma unroll
    for (int q = 0; q < 4; q++) {
        uint4 v = *reinterpret_cast<const uint4*>(arow + kk + lh * 32 + q * 8);
        st_sw(At, bo + q * 16, v);
    }
}

// ---------------------------------------------------------------------------
// scratch
// ---------------------------------------------------------------------------
__device__ int    g_ti[T_ * KTOP];
__device__ float  g_tw[T_ * KTOP];
__device__ int    g_cnt[E_];
__device__ int    g_slotTok[E_ * C_];
__device__ float  g_slotW[E_ * C_];
__device__ __half g_hbuf[(size_t)E_ * C_ * I_];
__device__ __half g_hsh[(size_t)T_ * I_];

// ---------------------------------------------------------------------------
// routing + dispatch
// ---------------------------------------------------------------------------
__global__ void routing_kernel(const float* __restrict__ x,
                               const float* __restrict__ gw) {
    __shared__ float lg[8][E_];
    int tid  = threadIdx.x;
    int tok0 = blockIdx.x * 8;
    #pragma unroll
    for (int p = 0; p < 2; p++) {
        int pair = tid + p * 256;
        int tk = pair >> 6, e = pair & 63;
        const float* xr = x  + (size_t)(tok0 + tk) * H_;
        const float* wr = gw + (size_t)e * H_;
        float acc = 0.f;
        for (int h = 0; h < H_; h += 4) {
            float4 a = *(const float4*)(xr + h);
            float4 b = *(const float4*)(wr + h);
            acc += a.x * b.x + a.y * b.y + a.z * b.z + a.w * b.w;
        }
        lg[tk][e] = acc;
    }
    __syncthreads();
    if (tid < 8) {
        int t = tok0 + tid;
        unsigned long long used = 0ull;
        float v[KTOP]; int id[KTOP];
        #pragma unroll
        for (int k = 0; k < KTOP; k++) {
            float best = -INFINITY; int bi = 0;
            for (int e = 0; e < E_; e++)
                if (!((used >> e) & 1ull) && lg[tid][e] > best) { best = lg[tid][e]; bi = e; }
            v[k] = best; id[k] = bi; used |= 1ull << bi;
        }
        float mx = v[0], w[KTOP], sum = 0.f;
        #pragma unroll
        for (int k = 0; k < KTOP; k++) { w[k] = expf(v[k] - mx); sum += w[k]; }
        #pragma unroll
        for (int k = 0; k < KTOP; k++) {
            g_ti[t * KTOP + k] = id[k];
            g_tw[t * KTOP + k] = w[k] / sum;
        }
    }
}

__global__ void dispatch_kernel() {
    __shared__ int sti[T_ * KTOP];
    int tid = threadIdx.x;
    for (int i = tid; i < T_ * KTOP; i += blockDim.x) sti[i] = g_ti[i];
    __syncthreads();
    int wid = tid >> 5, lane = tid & 31;
    int e = blockIdx.x * (blockDim.x >> 5) + wid;
    if (e < E_) {
        int cnt = 0;
        for (int base = 0; base < T_ * KTOP; base += 32) {
            int a = base + lane;
            bool m = (sti[a] == e);
            unsigned msk = __ballot_sync(0xffffffffu, m);
            if (m) {
                int c = cnt + __popc(msk & ((1u << lane) - 1u));
                if (c < C_) {
                    g_slotTok[e * C_ + c] = a >> 2;
                    g_slotW[e * C_ + c]   = g_tw[a];
                }
            }
            cnt += __popc(msk);
        }
        if (lane == 0) g_cnt[e] = cnt < C_ ? cnt : C_;
    }
}

// SMEM layout (shared by both paths)
#define OFF_A  1024
#define OFF_BG 33792
#define OFF_BU 66560
#define SM1    99328
#define SM2    66560
#define STG    16384

#if TC_OK
// ===========================================================================
// tcgen05 path (sm_103a / sm_100a)
// ===========================================================================
#define TC_ALLOC(sm, n)  asm volatile("tcgen05.alloc.cta_group::1.sync.aligned.shared::cta.b32 [%0], %1;" :: "r"(sm), "r"(n) : "memory")
#define TC_DEALLOC(tb,n) asm volatile("tcgen05.dealloc.cta_group::1.sync.aligned.b32 %0, %1;" :: "r"(tb), "r"(n))
#define TC_RELINQ()      asm volatile("tcgen05.relinquish_alloc_permit.cta_group::1.sync.aligned;")
#define TC_COMMIT(bar)   asm volatile("tcgen05.commit.cta_group::1.mbarrier::arrive::one.shared::cluster.b64 [%0];" :: "r"(bar) : "memory")
#define TC_FENCE_AFTER()  asm volatile("tcgen05.fence::after_thread_sync;" ::: "memory")
#define TC_FENCE_BEFORE() asm volatile("tcgen05.fence::before_thread_sync;" ::: "memory")
#define TC_WAIT_LD()      asm volatile("tcgen05.wait::ld.sync.aligned;" ::: "memory")
#define FENCE_ASYNC()     asm volatile("fence.proxy.async.shared::cta;" ::: "memory")
#define MBAR_INIT(a, c)  asm volatile("mbarrier.init.shared.b64 [%0], %1;" :: "r"(a), "r"(c) : "memory")
#define MBAR_INVAL(a)    asm volatile("mbarrier.inval.shared.b64 [%0];" :: "r"(a) : "memory")

#define MBAR_WAIT(addr, par) do {                                              \
    unsigned _m = (unsigned)(addr), _p = (unsigned)(par), _d;                  \
    asm volatile("{\n\t.reg .pred p;\n\t"                                      \
        "mbarrier.try_wait.parity.acquire.cta.shared::cta.b64 p, [%1], %2;\n\t"\
        "selp.b32 %0,1,0,p;\n\t}" : "=r"(_d) : "r"(_m), "r"(_p) : "memory");   \
    if (!_d) {                                                                 \
        asm volatile("{\n\t.reg .pred P1;\n\t"                                 \
        "WL_%=:\n\t"                                                           \
        "mbarrier.try_wait.parity.acquire.cta.shared::cta.b64 P1, [%0], %1, 0x989680;\n\t" \
        "@P1 bra.uni WD_%=;\n\t"                                               \
        "bra.uni WL_%=;\n\t"                                                   \
        "WD_%=:\n\t}" :: "r"(_m), "r"(_p) : "memory");                         \
    }                                                                          \
} while (0)

#define TC_LD32(r, ta) \
    asm volatile( \
        "tcgen05.ld.sync.aligned.32x32b.x32.b32 " \
        "{%0, %1, %2, %3, %4, %5, %6, %7, " \
        " %8, %9, %10, %11, %12, %13, %14, %15, " \
        " %16, %17, %18, %19, %20, %21, %22, %23, " \
        " %24, %25, %26, %27, %28, %29, %30, %31}, [%32];" \
        : "=r"((r)[0]),  "=r"((r)[1]),  "=r"((r)[2]),  "=r"((r)[3]), \
          "=r"((r)[4]),  "=r"((r)[5]),  "=r"((r)[6]),  "=r"((r)[7]), \
          "=r"((r)[8]),  "=r"((r)[9]),  "=r"((r)[10]), "=r"((r)[11]), \
          "=r"((r)[12]), "=r"((r)[13]), "=r"((r)[14]), "=r"((r)[15]), \
          "=r"((r)[16]), "=r"((r)[17]), "=r"((r)[18]), "=r"((r)[19]), \
          "=r"((r)[20]), "=r"((r)[21]), "=r"((r)[22]), "=r"((r)[23]), \
          "=r"((r)[24]), "=r"((r)[25]), "=r"((r)[26]), "=r"((r)[27]), \
          "=r"((r)[28]), "=r"((r)[29]), "=r"((r)[30]), "=r"((r)[31]) \
        : "r"(ta))

// idesc: dtype=F32, atype=btype=FP16 (=0), N=128, M=128
#define IDESC_F16 ((1u << 4) | (16u << 17) | (8u << 24))

__device__ __forceinline__ void mma_f16_ss(unsigned d, unsigned long long a,
                                           unsigned long long b, unsigned en) {
    asm volatile("{\n\t.reg .pred p;\n\tsetp.ne.u32 p, %4, 0;\n\t"
        "tcgen05.mma.cta_group::1.kind::f16 [%0], %1, %2, %3, {%5,%5,%5,%5}, p;\n\t}"
        :: "r"(d), "l"(a), "l"(b), "r"(IDESC_F16), "r"(en), "r"(0u) : "memory");
}
__device__ __forceinline__ unsigned long long make_desc(unsigned addr) {
    return ((unsigned long long)2 << 61) | ((unsigned long long)1 << 46)
         | ((unsigned long long)64 << 32) | ((unsigned long long)1 << 16)
         | ((addr >> 4) & 0x3FFFu);
}

template <bool EXP>
__global__ __launch_bounds__(256, 2) void mma_gemm1(
    const float* __restrict__ x,
    const int* __restrict__ gp, const float* __restrict__ gsc,
    const int* __restrict__ upk, const float* __restrict__ usc) {
    constexpr int NC = H_ / 64;   // 32
    extern __shared__ char smem[];
    const int tid = threadIdx.x, wid = tid >> 5, lid = tid & 31;
    const int j0 = blockIdx.x * 128;
    int e, m0, nrows;
    if (EXP) { e = blockIdx.y; m0 = 0; nrows = g_cnt[e]; if (nrows == 0) return; }
    else     { e = 0; m0 = blockIdx.y * 128; nrows = 128; }

    unsigned sb = smem_u32(smem);
    if (wid == 0) TC_ALLOC(sb, 256);
    if (tid == 0) { MBAR_INIT(sb + 8, 1); MBAR_INIT(sb + 16, 1); }
    __syncthreads();
    unsigned tb;
    asm("ld.shared.b32 %0, [%1];" : "=r"(tb) : "r"(sb));

    const int lrow = tid >> 1, lh = tid & 1;
    const float* arow = nullptr;
    if (EXP) { if (lrow < nrows) arow = x + (size_t)g_slotTok[e * C_ + lrow] * H_; }
    else       arow = x + (size_t)(m0 + lrow) * H_;

    const int* gpr = gp  + ((size_t)e * I_ + j0 + lrow) * (H_ / 8) + lh * 4;
    const int* upr = upk + ((size_t)e * I_ + j0 + lrow) * (H_ / 8) + lh * 4;
    const float* gsp = gsc + (size_t)e * (H_ / GS_) * I_ + j0 + lrow;
    const float* usp = usc + (size_t)e * (H_ / GS_) * I_ + j0 + lrow;
    const int bo = lrow * 128 + lh * 64;

    // prefetch chunk 0
    int4 wg = *(const int4*)gpr;
    int4 wu = *(const int4*)upr;
    unsigned sg2 = pack_sc(gsp[0]), su2 = pack_sc(usp[0]);

    int ph0 = 0, ph1 = 0;
    for (int c = 0; c < NC; c++) {
        const int s = c & 1;
        // prefetch next chunk (issued before the wait to hide LDG latency)
        int4 wgN = wg, wuN = wu; unsigned sg2N = sg2, su2N = su2;
        if (c + 1 < NC) {
            wgN  = *(const int4*)(gpr + ((c + 1) << 3));
            wuN  = *(const int4*)(upr + ((c + 1) << 3));
            sg2N = pack_sc(gsp[(size_t)((c + 1) >> 1) * I_]);
            su2N = pack_sc(usp[(size_t)((c + 1) >> 1) * I_]);
        }
        if (c >= 2) {
            if (s == 0) { MBAR_WAIT(sb + 8,  ph0); ph0 ^= 1; }
            else        { MBAR_WAIT(sb + 16, ph1); ph1 ^= 1; }
        }
        const int kk = c * 64;
        char* At = smem + OFF_A  + s * STG;
        char* Bg = smem + OFF_BG + s * STG;
        char* Bu = smem + OFF_BU + s * STG;
        if (arow) stage_A_f32(At, arow, kk, bo, lh);
        stage_B(Bg, wg, sg2, bo);
        stage_B(Bu, wu, su2, bo);
        FENCE_ASYNC();
        __syncthreads();
        if (tid == 0) {
            unsigned long long ad = make_desc(sb + OFF_A  + s * STG);
            unsigned long long gd = make_desc(sb + OFF_BG + s * STG);
            unsigned long long ud = make_desc(sb + OFF_BU + s * STG);
            #pragma unroll
            for (int ks = 0; ks < 4; ks++) {
                unsigned en = (c > 0 || ks > 0) ? 1u : 0u;
                mma_f16_ss(tb,        ad + ks * 2, gd + ks * 2, en);
                mma_f16_ss(tb + 128,  ad + ks * 2, ud + ks * 2, en);
            }
            TC_COMMIT(sb + 8 + 8 * s);
        }
        wg = wgN; wu = wuN; sg2 = sg2N; su2 = su2N;
    }
    MBAR_WAIT(sb + 16, ph1);
    TC_FENCE_AFTER();

    const int w4 = wid & 3, hf = wid >> 2;
    const int r = w4 * 32 + lid;
    bool valid = EXP ? (r < nrows) : true;
    __half* drow = EXP ? (g_hbuf + ((size_t)e * C_ + r) * I_)
                       : (g_hsh  + (size_t)(m0 + r) * I_);
    #pragma unroll
    for (int b = 0; b < 2; b++) {
        int cb = hf * 64 + b * 32;
        unsigned gr[32], ur[32];
        TC_LD32(gr, tb + cb);
        TC_LD32(ur, tb + 128 + cb);
        TC_WAIT_LD();
        if (valid) {
            #pragma unroll
            for (int q = 0; q < 4; q++) {
                float v[8];
                #pragma unroll
                for (int t = 0; t < 8; t++) {
                    int j = q * 8 + t;
                    float gv = __uint_as_float(gr[j]);
                    float uv = __uint_as_float(ur[j]);
                    v[t] = gv / (1.f + __expf(-gv)) * uv;
                }
                uint4 o;
                o.x = h2u(__float22half2_rn(make_float2(v[0], v[1])));
                o.y = h2u(__float22half2_rn(make_float2(v[2], v[3])));
                o.z = h2u(__float22half2_rn(make_float2(v[4], v[5])));
                o.w = h2u(__float22half2_rn(make_float2(v[6], v[7])));
                *reinterpret_cast<uint4*>(drow + j0 + cb + q * 8) = o;
            }
        }
    }
    TC_FENCE_BEFORE();
    __syncthreads();
    if (tid == 0) { MBAR_INVAL(sb + 8); MBAR_INVAL(sb + 16); }
    __syncthreads();
    if (wid == 0) { TC_RELINQ(); TC_DEALLOC(tb, 256); }
}

template <bool EXP>
__global__ __launch_bounds__(256, 2) void mma_gemm2(
    const int* __restrict__ dp, const float* __restrict__ dsc,
    float* __restrict__ y) {
    constexpr int NC = I_ / 64;   // 24
    extern __shared__ char smem[];
    const int tid = threadIdx.x, wid = tid >> 5, lid = tid & 31;
    const int n0 = blockIdx.x * 128;
    int e, m0, nrows;
    if (EXP) { e = blockIdx.y; m0 = 0; nrows = g_cnt[e]; if (nrows == 0) return; }
    else     { e = 0; m0 = blockIdx.y * 128; nrows = 128; }

    unsigned sb = smem_u32(smem);
    if (wid == 0) TC_ALLOC(sb, 128);
    if (tid == 0) { MBAR_INIT(sb + 8, 1); MBAR_INIT(sb + 16, 1); }
    __syncthreads();
    unsigned tb;
    asm("ld.shared.b32 %0, [%1];" : "=r"(tb) : "r"(sb));

    const int lrow = tid >> 1, lh = tid & 1;
    const __half* arow = EXP ? (g_hbuf + ((size_t)e * C_ + lrow) * I_)
                             : (g_hsh  + (size_t)(m0 + lrow) * I_);
    const int* dpr = dp + ((size_t)e * H_ + n0 + lrow) * (I_ / 8) + lh * 4;
    const float* dsp = dsc + (size_t)e * (I_ / GS_) * H_ + n0 + lrow;
    const int bo = lrow * 128 + lh * 64;

    // prefetch chunk 0 (weights + A)
    int4 wd = *(const int4*)dpr;
    unsigned sd2 = pack_sc(dsp[0]);
    uint4 a0 = *reinterpret_cast<const uint4*>(arow + lh * 32 + 0);
    uint4 a1 = *reinterpret_cast<const uint4*>(arow + lh * 32 + 8);
    uint4 a2 = *reinterpret_cast<const uint4*>(arow + lh * 32 + 16);
    uint4 a3 = *reinterpret_cast<const uint4*>(arow + lh * 32 + 24);

    int ph0 = 0, ph1 = 0;
    for (int c = 0; c < NC; c++) {
        const int s = c & 1;
        int4 wdN = wd; unsigned sd2N = sd2;
        uint4 b0 = a0, b1 = a1, b2 = a2, b3 = a3;
        if (c + 1 < NC) {
            const int kn = (c + 1) * 64 + lh * 32;
            wdN  = *(const int4*)(dpr + ((c + 1) << 3));
            sd2N = pack_sc(dsp[(size_t)((c + 1) >> 1) * H_]);
            a0 = *reinterpret_cast<const uint4*>(arow + kn + 0);
            a1 = *reinterpret_cast<const uint4*>(arow + kn + 8);
            a2 = *reinterpret_cast<const uint4*>(arow + kn + 16);
            a3 = *reinterpret_cast<const uint4*>(arow + kn + 24);
        }
        if (c >= 2) {
            if (s == 0) { MBAR_WAIT(sb + 8,  ph0); ph0 ^= 1; }
            else        { MBAR_WAIT(sb + 16, ph1); ph1 ^= 1; }
        }
        char* At = smem + OFF_A  + s * STG;
        char* Bt = smem + OFF_BG + s * STG;
        st_sw(At, bo + 0,  b0);
        st_sw(At, bo + 16, b1);
        st_sw(At, bo + 32, b2);
        st_sw(At, bo + 48, b3);
        stage_B(Bt, wd, sd2, bo);
        FENCE_ASYNC();
        __syncthreads();
        if (tid == 0) {
            unsigned long long ad = make_desc(sb + OFF_A  + s * STG);
            unsigned long long bd = make_desc(sb + OFF_BG + s * STG);
            #pragma unroll
            for (int ks = 0; ks < 4; ks++) {
                unsigned en = (c > 0 || ks > 0) ? 1u : 0u;
                mma_f16_ss(tb, ad + ks * 2, bd + ks * 2, en);
            }
            TC_COMMIT(sb + 8 + 8 * s);
        }
        wd = wdN; sd2 = sd2N;
    }
    MBAR_WAIT(sb + 16, ph1);
    TC_FENCE_AFTER();

    const int w4 = wid & 3, hf = wid >> 2;
    const int r = w4 * 32 + lid;
    bool valid = EXP ? (r < nrows) : true;
    int   tok = 0; float wgt = 1.f;
    if (EXP && valid) { tok = g_slotTok[e * C_ + r]; wgt = g_slotW[e * C_ + r]; }
    #pragma unroll
    for (int b = 0; b < 2; b++) {
        int cb = hf * 64 + b * 32;
        unsigned dr[32];
        TC_LD32(dr, tb + cb);
        TC_WAIT_LD();
        if (valid) {
            if (EXP) {
                float* dst = y + (size_t)tok * H_ + n0 + cb;
                #pragma unroll
                for (int j = 0; j < 32; j++)
                    atomicAdd(dst + j, wgt * __uint_as_float(dr[j]));
            } else {
                float* dst = y + (size_t)(m0 + r) * H_ + n0 + cb;
                #pragma unroll
                for (int j = 0; j < 32; j++)
                    dst[j] = __uint_as_float(dr[j]);
            }
        }
    }
    TC_FENCE_BEFORE();
    __syncthreads();
    if (tid == 0) { MBAR_INVAL(sb + 8); MBAR_INVAL(sb + 16); }
    __syncthreads();
    if (wid == 0) { TC_RELINQ(); TC_DEALLOC(tb, 128); }
}

#else  // !TC_OK
// ===========================================================================
// fallback path: mma.sync.m16n8k16 (HMMA) — compiles for plain sm_103
// ===========================================================================
__device__ __forceinline__ void ldm_x4(unsigned r[4], unsigned a) {
    asm volatile("ldmatrix.sync.aligned.m8n8.x4.shared.b16 {%0,%1,%2,%3}, [%4];"
                 : "=r"(r[0]), "=r"(r[1]), "=r"(r[2]), "=r"(r[3]) : "r"(a));
}
__device__ __forceinline__ void ldm_x2(unsigned r[2], unsigned a) {
    asm volatile("ldmatrix.sync.aligned.m8n8.x2.shared.b16 {%0,%1}, [%2];"
                 : "=r"(r[0]), "=r"(r[1]) : "r"(a));
}
__device__ __forceinline__ void mma16816(float* d, const unsigned* a, const unsigned* b) {
    asm volatile("mma.sync.aligned.m16n8k16.row.col.f32.f16.f16.f32 "
        "{%0,%1,%2,%3}, {%4,%5,%6,%7}, {%8,%9}, {%0,%1,%2,%3};"
        : "+f"(d[0]), "+f"(d[1]), "+f"(d[2]), "+f"(d[3])
        : "r"(a[0]), "r"(a[1]), "r"(a[2]), "r"(a[3]), "r"(b[0]), "r"(b[1]));
}

template <bool EXP>
__global__ __launch_bounds__(256) void mma_gemm1(
    const float* __restrict__ x,
    const int* __restrict__ gp, const float* __restrict__ gsc,
    const int* __restrict__ upk, const float* __restrict__ usc) {
    constexpr int NC = H_ / 64;
    extern __shared__ char smem[];
    const int tid = threadIdx.x, wid = tid >> 5, lane = tid & 31;
    const int j0 = blockIdx.x * 128;
    int e, m0, nrows;
    if (EXP) { e = blockIdx.y; m0 = 0; nrows = g_cnt[e]; if (nrows == 0) return; }
    else     { e = 0; m0 = blockIdx.y * 128; nrows = 128; }

    unsigned sb = smem_u32(smem);
    const unsigned Ab = sb + OFF_A, Bgb = sb + OFF_BG, Bub = sb + OFF_BU;

    const int lrow = tid >> 1, lh = tid & 1;
    const float* arow = nullptr;
    if (EXP) { if (lrow < nrows) arow = x + (size_t)g_slotTok[e * C_ + lrow] * H_; }
    else       arow = x + (size_t)(m0 + lrow) * H_;
    const int* gpr = gp  + ((size_t)e * I_ + j0 + lrow) * (H_ / 8) + lh * 4;
    const int* upr = upk + ((size_t)e * I_ + j0 + lrow) * (H_ / 8) + lh * 4;
    const float* gsp = gsc + (size_t)e * (H_ / GS_) * I_ + j0 + lrow;
    const float* usp = usc + (size_t)e * (H_ / GS_) * I_ + j0 + lrow;
    const int bo = lrow * 128 + lh * 64;

    const int wm = wid >> 2, wn = wid & 3;          // warp tile 64 x 32

    float ag[4][4][4], au[4][4][4];
    #pragma unroll
    for (int i = 0; i < 4; i++)
        #pragma unroll
        for (int j = 0; j < 4; j++)
            #pragma unroll
            for (int q = 0; q < 4; q++) { ag[i][j][q] = 0.f; au[i][j][q] = 0.f; }

    for (int c = 0; c < NC; c++) {
        int kk = c * 64;
        if (arow) stage_A_f32(smem + OFF_A, arow, kk, bo, lh);
        stage_B(smem + OFF_BG, *(const int4*)(gpr + (kk >> 3)),
                pack_sc(gsp[(size_t)(kk >> 7) * I_]), bo);
        stage_B(smem + OFF_BU, *(const int4*)(upr + (kk >> 3)),
                pack_sc(usp[(size_t)(kk >> 7) * I_]), bo);
        __syncthreads();

        #pragma unroll
        for (int ks = 0; ks < 4; ks++) {
            unsigned af[4][4];
            #pragma unroll
            for (int mt = 0; mt < 4; mt++)
                ldm_x4(af[mt], swadr(Ab, wm * 64 + mt * 16 + (lane & 15),
                                     ks * 32 + (lane >> 4) * 16));
            #pragma unroll
            for (int nt = 0; nt < 4; nt++) {
                int brow = wn * 32 + nt * 8 + (lane & 7);
                int bcol = ks * 32 + ((lane >> 3) & 1) * 16;
                unsigned bg[2], bu[2];
                ldm_x2(bg, swadr(Bgb, brow, bcol));
                ldm_x2(bu, swadr(Bub, brow, bcol));
                #pragma unroll
                for (int mt = 0; mt < 4; mt++) {
                    mma16816(ag[mt][nt], af[mt], bg);
                    mma16816(au[mt][nt], af[mt], bu);
                }
            }
        }
        __syncthreads();
    }

    const int g = lane >> 2, cq = lane & 3;
    #pragma unroll
    for (int mt = 0; mt < 4; mt++) {
        #pragma unroll
        for (int nt = 0; nt < 4; nt++) {
            int nn = j0 + wn * 32 + nt * 8 + cq * 2;
            #pragma unroll
            for (int hrow = 0; hrow < 2; hrow++) {
                int r = wm * 64 + mt * 16 + g + hrow * 8;
                if (EXP && r >= nrows) continue;
                float g0 = ag[mt][nt][hrow * 2], g1 = ag[mt][nt][hrow * 2 + 1];
                float u0 = au[mt][nt][hrow * 2], u1 = au[mt][nt][hrow * 2 + 1];
                float v0 = g0 / (1.f + expf(-g0)) * u0;
                float v1 = g1 / (1.f + expf(-g1)) * u1;
                __half* dst = (EXP ? g_hbuf + ((size_t)e * C_ + r) * I_
                                   : g_hsh + (size_t)(m0 + r) * I_) + nn;
                *reinterpret_cast<__half2*>(dst) =
                    __float22half2_rn(make_float2(v0, v1));
            }
        }
    }
}

template <bool EXP>
__global__ __launch_bounds__(256) void mma_gemm2(
    const int* __restrict__ dp, const float* __restrict__ dsc,
    float* __restrict__ y) {
    constexpr int NC = I_ / 64;
    extern __shared__ char smem[];
    const int tid = threadIdx.x, wid = tid >> 5, lane = tid & 31;
    const int n0 = blockIdx.x * 128;
    int e, m0, nrows;
    if (EXP) { e = blockIdx.y; m0 = 0; nrows = g_cnt[e]; if (nrows == 0) return; }
    else     { e = 0; m0 = blockIdx.y * 128; nrows = 128; }

    unsigned sb = smem_u32(smem);
    const unsigned Ab = sb + OFF_A, Bb = sb + OFF_BG;

    const int lrow = tid >> 1, lh = tid & 1;
    const __half* arow = EXP ? (g_hbuf + ((size_t)e * C_ + lrow) * I_)
                             : (g_hsh  + (size_t)(m0 + lrow) * I_);
    const int* dpr = dp + ((size_t)e * H_ + n0 + lrow) * (I_ / 8) + lh * 4;
    const float* dsp = dsc + (size_t)e * (I_ / GS_) * H_ + n0 + lrow;
    const int bo = lrow * 128 + lh * 64;

    const int wm = wid >> 2, wn = wid & 3;

    float acc[4][4][4];
    #pragma unroll
    for (int i = 0; i < 4; i++)
        #pragma unroll
        for (int j = 0; j < 4; j++)
            #pragma unroll
            for (int q = 0; q < 4; q++) acc[i][j][q] = 0.f;

    for (int c = 0; c < NC; c++) {
        int kk = c * 64;
        stage_A_f16(smem + OFF_A, arow, kk, bo, lh);
        stage_B(smem + OFF_BG, *(const int4*)(dpr + (kk >> 3)),
                pack_sc(dsp[(size_t)(kk >> 7) * H_]), bo);
        __syncthreads();

        #pragma unroll
        for (int ks = 0; ks < 4; ks++) {
            unsigned af[4][4];
            #pragma unroll
            for (int mt = 0; mt < 4; mt++)
                ldm_x4(af[mt], swadr(Ab, wm * 64 + mt * 16 + (lane & 15),
                                     ks * 32 + (lane >> 4) * 16));
            #pragma unroll
            for (int nt = 0; nt < 4; nt++) {
                int brow = wn * 32 + nt * 8 + (lane & 7);
                int bcol = ks * 32 + ((lane >> 3) & 1) * 16;
                unsigned bf[2];
                ldm_x2(bf, swadr(Bb, brow, bcol));
                #pragma unroll
                for (int mt = 0; mt < 4; mt++)
                    mma16816(acc[mt][nt], af[mt], bf);
            }
        }
        __syncthreads();
    }

    const int g = lane >> 2, cq = lane & 3;
    #pragma unroll
    for (int mt = 0; mt < 4; mt++) {
        #pragma unroll
        for (int hrow = 0; hrow < 2; hrow++) {
            int r = wm * 64 + mt * 16 + g + hrow * 8;
            if (EXP && r >= nrows) continue;
            int tok = 0; float wgt = 1.f;
            if (EXP) { tok = g_slotTok[e * C_ + r]; wgt = g_slotW[e * C_ + r]; }
            #pragma unroll
            for (int nt = 0; nt < 4; nt++) {
                int nn = n0 + wn * 32 + nt * 8 + cq * 2;
                float v0 = acc[mt][nt][hrow * 2], v1 = acc[mt][nt][hrow * 2 + 1];
                if (EXP) {
                    float* dst = y + (size_t)tok * H_ + nn;
                    atomicAdd(dst,     wgt * v0);
                    atomicAdd(dst + 1, wgt * v1);
                } else {
                    float* dst = y + (size_t)(m0 + r) * H_ + nn;
                    dst[0] = v0; dst[1] = v1;
                }
            }
        }
    }
}
#endif  // TC_OK

// ---------------------------------------------------------------------------
// launch
// ---------------------------------------------------------------------------
extern "C" void kernel_launch(void* const* d_in, const int* in_sizes, int n_in,
                              void* d_out, int out_size) {
    const float* x   = (const float*)d_in[0];
    const float* gw  = (const float*)d_in[1];
    const float* gsc = (const float*)d_in[2];
    const float* usc = (const float*)d_in[3];
    const float* dsc = (const float*)d_in[4];
    const float* sgs = (const float*)d_in[5];
    const float* sus = (const float*)d_in[6];
    const float* sds = (const float*)d_in[7];
    const int*   gpk = (const int*)d_in[8];
    const int*   upk = (const int*)d_in[9];
    const int*   dpk = (const int*)d_in[10];
    const int*   sgp = (const int*)d_in[11];
    const int*   sup = (const int*)d_in[12];
    const int*   sdp = (const int*)d_in[13];
    float* y = (float*)d_out;

    cudaFuncSetAttribute(mma_gemm1<true>,  cudaFuncAttributeMaxDynamicSharedMemorySize, SM1);
    cudaFuncSetAttribute(mma_gemm1<false>, cudaFuncAttributeMaxDynamicSharedMemorySize, SM1);
    cudaFuncSetAttribute(mma_gemm2<true>,  cudaFuncAttributeMaxDynamicSharedMemorySize, SM2);
    cudaFuncSetAttribute(mma_gemm2<false>, cudaFuncAttributeMaxDynamicSharedMemorySize, SM2);

    routing_kernel<<<T_ / 8, 256>>>(x, gw);
    dispatch_kernel<<<2, 1024>>>();

    // stage 1: SwiGLU intermediates
    mma_gemm1<true><<<dim3(I_ / 128, E_), 256, SM1>>>(x, gpk, gsc, upk, usc);
    mma_gemm1<false><<<dim3(I_ / 128, T_ / 128), 256, SM1>>>(x, sgp, sgs, sup, sus);

    // stage 2: shared expert writes y first (initializes output), experts add
    mma_gemm2<false><<<dim3(H_ / 128, T_ / 128), 256, SM2>>>(sdp, sds, y);
    mma_gemm2<true><<<dim3(H_ / 128, E_), 256, SM2>>>(dpk, dsc, y);
}

// round 6
// speedup vs baseline: 6.3105x; 1.0407x over previous
#include <cuda_runtime.h>
#include <cuda_fp16.h>
#include <math.h>

#define E_   64
#define KTOP 4
#define H_   2048
#define I_   1536
#define GS_  128
#define T_   1024
#define C_   128

// Does this device pass support tcgen05 (arch-accelerated sm_100a/sm_103a)?
#if defined(__CUDA_ARCH__) && !defined(__CUDA_ARCH_FEAT_SM103_ALL) && !defined(__CUDA_ARCH_FEAT_SM100_ALL)
#define TC_OK 0
#else
#define TC_OK 1
#endif

// ---------------------------------------------------------------------------
// common helpers
// ---------------------------------------------------------------------------
__device__ __forceinline__ unsigned smem_u32(const void* p) {
    unsigned a;
    asm("{ .reg .u64 t; cvta.to.shared.u64 t, %1; cvt.u32.u64 %0, t; }" : "=r"(a) : "l"(p));
    return a;
}
__device__ __forceinline__ unsigned h2u(__half2 h) {
    return *reinterpret_cast<unsigned*>(&h);
}
__device__ __forceinline__ unsigned swoff(int off) {
    return (unsigned)(off ^ ((off >> 3) & 0x70));
}
__device__ __forceinline__ void st_sw(char* base, int off, uint4 v) {
    *reinterpret_cast<uint4*>(base + swoff(off)) = v;
}
__device__ __forceinline__ unsigned swadr(unsigned base, int row, int col) {
    return base + swoff(row * 128 + col);
}
__device__ __forceinline__ unsigned pack_sc(float s) {
    return h2u(__float2half2_rn(s));
}

// cp.async helpers
__device__ __forceinline__ void cpa16(unsigned dst, const void* src) {
    asm volatile("cp.async.ca.shared.global [%0], [%1], 16;" :: "r"(dst), "l"(src));
}
#define CP_COMMIT() asm volatile("cp.async.commit_group;" ::: "memory")
#define CP_WAIT(n)  asm volatile("cp.async.wait_group %0;" :: "n"(n) : "memory")

// FP4 E2M1 x8 -> 8 fp16 via PRMT tables; sc2 = half2(scale, scale)
__device__ __forceinline__ uint4 dec8p(unsigned w, unsigned sc2) {
    const unsigned tLo = 0x3E3C3800u, tHi = 0x46444240u;
    unsigned m0, m1;
    asm("prmt.b32 %0,%1,%2,%3;" : "=r"(m0) : "r"(tLo), "r"(tHi), "r"(w & 0x7777u));
    asm("prmt.b32 %0,%1,%2,%3;" : "=r"(m1) : "r"(tLo), "r"(tHi), "r"((w >> 16) & 0x7777u));
    unsigned q4 = (w << 4) & 0x80808080u;
    unsigned q0 = w & 0x80808080u;
    unsigned r[4];
    #pragma unroll
    for (int p = 0; p < 4; p++) {
        unsigned mag  = (p < 2) ? m0 : m1;
        unsigned mctl = (p & 1) ? 0x3424u : 0x1404u;
        unsigned me, se;
        asm("prmt.b32 %0,%1,%2,%3;" : "=r"(me) : "r"(mag), "r"(0u), "r"(mctl));
        unsigned sctl = 0x4000u + (unsigned)p * 0x1010u;
        asm("prmt.b32 %0,%1,%2,%3;" : "=r"(se) : "r"(q4), "r"(q0), "r"(sctl));
        unsigned v = me | (se & 0x80008000u);
        asm("mul.rn.f16x2 %0,%1,%2;" : "=r"(r[p]) : "r"(v), "r"(sc2));
    }
    return make_uint4(r[0], r[1], r[2], r[3]);
}

__device__ __forceinline__ void stage_B(char* Bt, int4 w, unsigned sc2, int bo) {
    st_sw(Bt, bo + 0,  dec8p((unsigned)w.x, sc2));
    st_sw(Bt, bo + 16, dec8p((unsigned)w.y, sc2));
    st_sw(Bt, bo + 32, dec8p((unsigned)w.z, sc2));
    st_sw(Bt, bo + 48, dec8p((unsigned)w.w, sc2));
}

// load 32 fp32 -> 4 converted uint4 (fp16x2)
__device__ __forceinline__ void ldcvtA(const float* arow, int kk, int lh, uint4* o) {
    if (!arow) return;
    const float* p = arow + kk + lh * 32;
    #pragma unroll
    for (int q = 0; q < 4; q++) {
        float4 fa = *(const float4*)(p + q * 8);
        float4 fb = *(const float4*)(p + q * 8 + 4);
        o[q].x = h2u(__float22half2_rn(make_float2(fa.x, fa.y)));
        o[q].y = h2u(__float22half2_rn(make_float2(fa.z, fa.w)));
        o[q].z = h2u(__float22half2_rn(make_float2(fb.x, fb.y)));
        o[q].w = h2u(__float22half2_rn(make_float2(fb.z, fb.w)));
    }
}
__device__ __forceinline__ void stage_A_f32(char* At, const float* arow, int kk,
                                            int bo, int lh) {
    uint4 t[4];
    ldcvtA(arow, kk, lh, t);
    st_sw(At, bo + 0,  t[0]); st_sw(At, bo + 16, t[1]);
    st_sw(At, bo + 32, t[2]); st_sw(At, bo + 48, t[3]);
}
__device__ __forceinline__ void stage_A_f16(char* At, const __half* arow, int kk,
                                            int bo, int lh) {
    #pragma unroll
    for (int q = 0; q < 4; q++) {
        uint4 v = *reinterpret_cast<const uint4*>(arow + kk + lh * 32 + q * 8);
        st_sw(At, bo + q * 16, v);
    }
}

// ---------------------------------------------------------------------------
// scratch
// ---------------------------------------------------------------------------
__device__ int    g_ti[T_ * KTOP];
__device__ float  g_tw[T_ * KTOP];
__device__ int    g_cnt[E_];
__device__ int    g_slotTok[E_ * C_];
__device__ float  g_slotW[E_ * C_];
__device__ __half g_hbuf[(size_t)E_ * C_ * I_];
__device__ __half g_hsh[(size_t)T_ * I_];

// ---------------------------------------------------------------------------
// routing + dispatch + zero
// ---------------------------------------------------------------------------
__global__ void routing_kernel(const float* __restrict__ x,
                               const float* __restrict__ gw) {
    __shared__ float lg[8][E_];
    int tid  = threadIdx.x;
    int tok0 = blockIdx.x * 8;
    #pragma unroll
    for (int p = 0; p < 2; p++) {
        int pair = tid + p * 256;
        int tk = pair >> 6, e = pair & 63;
        const float* xr = x  + (size_t)(tok0 + tk) * H_;
        const float* wr = gw + (size_t)e * H_;
        float acc = 0.f;
        for (int h = 0; h < H_; h += 4) {
            float4 a = *(const float4*)(xr + h);
            float4 b = *(const float4*)(wr + h);
            acc += a.x * b.x + a.y * b.y + a.z * b.z + a.w * b.w;
        }
        lg[tk][e] = acc;
    }
    __syncthreads();
    if (tid < 8) {
        int t = tok0 + tid;
        unsigned long long used = 0ull;
        float v[KTOP]; int id[KTOP];
        #pragma unroll
        for (int k = 0; k < KTOP; k++) {
            float best = -INFINITY; int bi = 0;
            for (int e = 0; e < E_; e++)
                if (!((used >> e) & 1ull) && lg[tid][e] > best) { best = lg[tid][e]; bi = e; }
            v[k] = best; id[k] = bi; used |= 1ull << bi;
        }
        float mx = v[0], w[KTOP], sum = 0.f;
        #pragma unroll
        for (int k = 0; k < KTOP; k++) { w[k] = expf(v[k] - mx); sum += w[k]; }
        #pragma unroll
        for (int k = 0; k < KTOP; k++) {
            g_ti[t * KTOP + k] = id[k];
            g_tw[t * KTOP + k] = w[k] / sum;
        }
    }
}

__global__ void dispatch_kernel() {
    __shared__ int sti[T_ * KTOP];
    int tid = threadIdx.x;
    for (int i = tid; i < T_ * KTOP; i += blockDim.x) sti[i] = g_ti[i];
    __syncthreads();
    int wid = tid >> 5, lane = tid & 31;
    int e = blockIdx.x * (blockDim.x >> 5) + wid;
    if (e < E_) {
        int cnt = 0;
        for (int base = 0; base < T_ * KTOP; base += 32) {
            int a = base + lane;
            bool m = (sti[a] == e);
            unsigned msk = __ballot_sync(0xffffffffu, m);
            if (m) {
                int c = cnt + __popc(msk & ((1u << lane) - 1u));
                if (c < C_) {
                    g_slotTok[e * C_ + c] = a >> 2;
                    g_slotW[e * C_ + c]   = g_tw[a];
                }
            }
            cnt += __popc(msk);
        }
        if (lane == 0) g_cnt[e] = cnt < C_ ? cnt : C_;
    }
}

__global__ void zero_y_kernel(float4* y) {
    y[(size_t)blockIdx.x * blockDim.x + threadIdx.x] = make_float4(0.f, 0.f, 0.f, 0.f);
}

// SMEM layouts (no overlaps; tiles 1024-aligned)
// gemm1: header[0,64) | PG ring 3x4096 [64,12352) | PU ring 3x4096 [12352,24640)
//        | A 3x16K @25600 | Bg 3x16K @74752 | Bu 3x16K @123904 | end 173056
#define G1_PG  64
#define G1_PU  12352
#define G1_A   25600
#define G1_BG  74752
#define G1_BU  123904
#define SM1    173056
// gemm2: header[0,64) | PB ring 2x4096 [64,8256) | A 3x16K @16384 | B 3x16K @65536
#define G2_PB  64
#define G2_A   16384
#define G2_B   65536
#define SM2    114688
#define STG    16384

#if TC_OK
// ===========================================================================
// tcgen05 path
// ===========================================================================
#define TC_ALLOC(sm, n)  asm volatile("tcgen05.alloc.cta_group::1.sync.aligned.shared::cta.b32 [%0], %1;" :: "r"(sm), "r"(n) : "memory")
#define TC_DEALLOC(tb,n) asm volatile("tcgen05.dealloc.cta_group::1.sync.aligned.b32 %0, %1;" :: "r"(tb), "r"(n))
#define TC_RELINQ()      asm volatile("tcgen05.relinquish_alloc_permit.cta_group::1.sync.aligned;")
#define TC_COMMIT(bar)   asm volatile("tcgen05.commit.cta_group::1.mbarrier::arrive::one.shared::cluster.b64 [%0];" :: "r"(bar) : "memory")
#define TC_FENCE_AFTER()  asm volatile("tcgen05.fence::after_thread_sync;" ::: "memory")
#define TC_FENCE_BEFORE() asm volatile("tcgen05.fence::before_thread_sync;" ::: "memory")
#define TC_WAIT_LD()      asm volatile("tcgen05.wait::ld.sync.aligned;" ::: "memory")
#define FENCE_ASYNC()     asm volatile("fence.proxy.async.shared::cta;" ::: "memory")
#define MBAR_INIT(a, c)  asm volatile("mbarrier.init.shared.b64 [%0], %1;" :: "r"(a), "r"(c) : "memory")
#define MBAR_INVAL(a)    asm volatile("mbarrier.inval.shared.b64 [%0];" :: "r"(a) : "memory")

#define MBAR_WAIT(addr, par) do {                                              \
    unsigned _m = (unsigned)(addr), _p = (unsigned)(par), _d;                  \
    asm volatile("{\n\t.reg .pred p;\n\t"                                      \
        "mbarrier.try_wait.parity.acquire.cta.shared::cta.b64 p, [%1], %2;\n\t"\
        "selp.b32 %0,1,0,p;\n\t}" : "=r"(_d) : "r"(_m), "r"(_p) : "memory");   \
    if (!_d) {                                                                 \
        asm volatile("{\n\t.reg .pred P1;\n\t"                                 \
        "WL_%=:\n\t"                                                           \
        "mbarrier.try_wait.parity.acquire.cta.shared::cta.b64 P1, [%0], %1, 0x989680;\n\t" \
        "@P1 bra.uni WD_%=;\n\t"                                               \
        "bra.uni WL_%=;\n\t"                                                   \
        "WD_%=:\n\t}" :: "r"(_m), "r"(_p) : "memory");                         \
    }                                                                          \
} while (0)

#define TC_LD32(r, ta) \
    asm volatile( \
        "tcgen05.ld.sync.aligned.32x32b.x32.b32 " \
        "{%0, %1, %2, %3, %4, %5, %6, %7, " \
        " %8, %9, %10, %11, %12, %13, %14, %15, " \
        " %16, %17, %18, %19, %20, %21, %22, %23, " \
        " %24, %25, %26, %27, %28, %29, %30, %31}, [%32];" \
        : "=r"((r)[0]),  "=r"((r)[1]),  "=r"((r)[2]),  "=r"((r)[3]), \
          "=r"((r)[4]),  "=r"((r)[5]),  "=r"((r)[6]),  "=r"((r)[7]), \
          "=r"((r)[8]),  "=r"((r)[9]),  "=r"((r)[10]), "=r"((r)[11]), \
          "=r"((r)[12]), "=r"((r)[13]), "=r"((r)[14]), "=r"((r)[15]), \
          "=r"((r)[16]), "=r"((r)[17]), "=r"((r)[18]), "=r"((r)[19]), \
          "=r"((r)[20]), "=r"((r)[21]), "=r"((r)[22]), "=r"((r)[23]), \
          "=r"((r)[24]), "=r"((r)[25]), "=r"((r)[26]), "=r"((r)[27]), \
          "=r"((r)[28]), "=r"((r)[29]), "=r"((r)[30]), "=r"((r)[31]) \
        : "r"(ta))

#define IDESC_F16 ((1u << 4) | (16u << 17) | (8u << 24))

__device__ __forceinline__ void mma_f16_ss(unsigned d, unsigned long long a,
                                           unsigned long long b, unsigned en) {
    asm volatile("{\n\t.reg .pred p;\n\tsetp.ne.u32 p, %4, 0;\n\t"
        "tcgen05.mma.cta_group::1.kind::f16 [%0], %1, %2, %3, {%5,%5,%5,%5}, p;\n\t}"
        :: "r"(d), "l"(a), "l"(b), "r"(IDESC_F16), "r"(en), "r"(0u) : "memory");
}
__device__ __forceinline__ unsigned long long make_desc(unsigned addr) {
    return ((unsigned long long)2 << 61) | ((unsigned long long)1 << 46)
         | ((unsigned long long)64 << 32) | ((unsigned long long)1 << 16)
         | ((addr >> 4) & 0x3FFFu);
}

__global__ __launch_bounds__(256) void mma_gemm1(
    const float* __restrict__ x,
    const int* __restrict__ gp, const float* __restrict__ gsc,
    const int* __restrict__ up, const float* __restrict__ usc,
    const int* __restrict__ sgp, const float* __restrict__ sgs,
    const int* __restrict__ sup, const float* __restrict__ sus) {
    constexpr int NC = H_ / 64;   // 32
    extern __shared__ char smem[];
    const int tid = threadIdx.x, wid = tid >> 5, lid = tid & 31;
    const int j0 = blockIdx.x * 128;
    const int by = blockIdx.y;
    const bool XP = by < E_;
    const int e  = XP ? by : 0;
    const int m0 = XP ? 0 : (by - E_) * 128;
    const int nrows = XP ? g_cnt[e] : 128;
    if (nrows == 0) return;

    unsigned sb = smem_u32(smem);
    if (wid == 0) TC_ALLOC(sb, 256);
    if (tid == 0) { MBAR_INIT(sb + 8, 1); MBAR_INIT(sb + 16, 1); MBAR_INIT(sb + 24, 1); }
    __syncthreads();
    unsigned tb;
    asm("ld.shared.b32 %0, [%1];" : "=r"(tb) : "r"(sb));

    const int lrow = tid >> 1, lh = tid & 1;
    const float* arow = nullptr;
    if (XP) { if (lrow < nrows) arow = x + (size_t)g_slotTok[e * C_ + lrow] * H_; }
    else      arow = x + (size_t)(m0 + lrow) * H_;

    const size_t wr0 = ((size_t)(XP ? e * I_ : 0) + j0 + lrow) * (H_ / 8) + lh * 4;
    const int* gpr = (XP ? gp  : sgp) + wr0;
    const int* upr = (XP ? up  : sup) + wr0;
    const size_t sc0 = (size_t)(XP ? e * (H_ / GS_) * I_ : 0) + j0 + lrow;
    const float* gsp = (XP ? gsc : sgs) + sc0;
    const float* usp = (XP ? usc : sus) + sc0;
    const int bo = lrow * 128 + lh * 64;

    // prologue: cp.async weight rings for chunks 0..2 (depth-3)
    #pragma unroll
    for (int p = 0; p < 3; p++) {
        cpa16(sb + G1_PG + p * 4096 + tid * 16, gpr + p * 8);
        cpa16(sb + G1_PU + p * 4096 + tid * 16, upr + p * 8);
        CP_COMMIT();
    }
    uint4 aP[4];
    ldcvtA(arow, 0, lh, aP);
    unsigned sg2 = pack_sc(gsp[0]), su2 = pack_sc(usp[0]);

    for (int c = 0; c < NC; c++) {
        const int st = c % 3;
        uint4 aN[4] = {};
        unsigned sg2N = sg2, su2N = su2;
        if (c + 1 < NC) {
            ldcvtA(arow, (c + 1) * 64, lh, aN);
            sg2N = pack_sc(gsp[(size_t)((c + 1) >> 1) * I_]);
            su2N = pack_sc(usp[(size_t)((c + 1) >> 1) * I_]);
        }
        if (c >= 3) MBAR_WAIT(sb + 8 + 8 * st, ((c - 3) / 3) & 1);  // MMA(c-3) done
        CP_WAIT(2);   // weight chunk c landed
        char* At = smem + G1_A  + st * STG;
        char* Bg = smem + G1_BG + st * STG;
        char* Bu = smem + G1_BU + st * STG;
        int4 wg = *(const int4*)(smem + G1_PG + st * 4096 + tid * 16);
        int4 wu = *(const int4*)(smem + G1_PU + st * 4096 + tid * 16);
        stage_B(Bg, wg, sg2, bo);
        stage_B(Bu, wu, su2, bo);
        if (arow) {
            st_sw(At, bo + 0,  aP[0]); st_sw(At, bo + 16, aP[1]);
            st_sw(At, bo + 32, aP[2]); st_sw(At, bo + 48, aP[3]);
        }
        if (c + 3 < NC) {
            cpa16(sb + G1_PG + st * 4096 + tid * 16, gpr + (c + 3) * 8);
            cpa16(sb + G1_PU + st * 4096 + tid * 16, upr + (c + 3) * 8);
        }
        CP_COMMIT();
        FENCE_ASYNC();
        __syncthreads();
        if (tid == 0) {
            unsigned long long ad = make_desc(sb + G1_A  + st * STG);
            unsigned long long gd = make_desc(sb + G1_BG + st * STG);
            unsigned long long ud = make_desc(sb + G1_BU + st * STG);
            #pragma unroll
            for (int ks = 0; ks < 4; ks++) {
                unsigned en = (c > 0 || ks > 0) ? 1u : 0u;
                mma_f16_ss(tb,       ad + ks * 2, gd + ks * 2, en);
                mma_f16_ss(tb + 128, ad + ks * 2, ud + ks * 2, en);
            }
            TC_COMMIT(sb + 8 + 8 * st);
        }
        aP[0] = aN[0]; aP[1] = aN[1]; aP[2] = aN[2]; aP[3] = aN[3];
        sg2 = sg2N; su2 = su2N;
    }
    {
        const int ls = (NC - 1) % 3;
        MBAR_WAIT(sb + 8 + 8 * ls, (((NC - 1) - ls) / 3) & 1);
    }
    TC_FENCE_AFTER();

    const int w4 = wid & 3, hf = wid >> 2;
    const int r = w4 * 32 + lid;
    bool valid = XP ? (r < nrows) : true;
    __half* drow = XP ? (g_hbuf + ((size_t)e * C_ + r) * I_)
                      : (g_hsh  + (size_t)(m0 + r) * I_);
    #pragma unroll
    for (int b = 0; b < 2; b++) {
        int cb = hf * 64 + b * 32;
        unsigned gr[32], ur[32];
        TC_LD32(gr, tb + cb);
        TC_LD32(ur, tb + 128 + cb);
        TC_WAIT_LD();
        if (valid) {
            #pragma unroll
            for (int q = 0; q < 4; q++) {
                float v[8];
                #pragma unroll
                for (int t = 0; t < 8; t++) {
                    int j = q * 8 + t;
                    float gv = __uint_as_float(gr[j]);
                    float uv = __uint_as_float(ur[j]);
                    v[t] = gv / (1.f + __expf(-gv)) * uv;
                }
                uint4 o;
                o.x = h2u(__float22half2_rn(make_float2(v[0], v[1])));
                o.y = h2u(__float22half2_rn(make_float2(v[2], v[3])));
                o.z = h2u(__float22half2_rn(make_float2(v[4], v[5])));
                o.w = h2u(__float22half2_rn(make_float2(v[6], v[7])));
                *reinterpret_cast<uint4*>(drow + j0 + cb + q * 8) = o;
            }
        }
    }
    TC_FENCE_BEFORE();
    __syncthreads();
    if (tid == 0) { MBAR_INVAL(sb + 8); MBAR_INVAL(sb + 16); MBAR_INVAL(sb + 24); }
    __syncthreads();
    if (wid == 0) { TC_RELINQ(); TC_DEALLOC(tb, 256); }
}

__global__ __launch_bounds__(256) void mma_gemm2(
    const int* __restrict__ dp, const float* __restrict__ dsc,
    const int* __restrict__ sdp, const float* __restrict__ sds,
    float* __restrict__ y) {
    constexpr int NC = I_ / 64;   // 24
    extern __shared__ char smem[];
    const int tid = threadIdx.x, wid = tid >> 5, lid = tid & 31;
    const int n0 = blockIdx.x * 128;
    const int by = blockIdx.y;
    const bool XP = by < E_;
    const int e  = XP ? by : 0;
    const int m0 = XP ? 0 : (by - E_) * 128;
    const int nrows = XP ? g_cnt[e] : 128;
    if (nrows == 0) return;

    unsigned sb = smem_u32(smem);
    if (wid == 0) TC_ALLOC(sb, 128);
    if (tid == 0) { MBAR_INIT(sb + 8, 1); MBAR_INIT(sb + 16, 1); MBAR_INIT(sb + 24, 1); }
    __syncthreads();
    unsigned tb;
    asm("ld.shared.b32 %0, [%1];" : "=r"(tb) : "r"(sb));

    const int lrow = tid >> 1, lh = tid & 1;
    const __half* arow = XP ? (g_hbuf + ((size_t)e * C_ + lrow) * I_)
                            : (g_hsh  + (size_t)(m0 + lrow) * I_);
    const int* dpr = (XP ? dp : sdp)
                   + ((size_t)(XP ? e * H_ : 0) + n0 + lrow) * (I_ / 8) + lh * 4;
    const float* dsp = (XP ? dsc : sds)
                     + (size_t)(XP ? e * (I_ / GS_) * H_ : 0) + n0 + lrow;
    const int bo = lrow * 128 + lh * 64;

    // prologue: Bp(0); A(0)->tile0; Bp(1)  (FIFO order matters)
    cpa16(sb + G2_PB + tid * 16, dpr);
    CP_COMMIT();
    #pragma unroll
    for (int q = 0; q < 4; q++)
        cpa16(sb + G2_A + swoff(bo + q * 16), arow + lh * 32 + q * 8);
    CP_COMMIT();
    cpa16(sb + G2_PB + 4096 + tid * 16, dpr + 8);
    CP_COMMIT();
    unsigned sd2 = pack_sc(dsp[0]);

    for (int c = 0; c < NC; c++) {
        const int st = c % 3;
        unsigned sd2N = sd2;
        if (c + 1 < NC) sd2N = pack_sc(dsp[(size_t)((c + 1) >> 1) * H_]);
        if (c >= 2) {
            int ws = (c - 2) % 3, wp2 = ((c - 2) / 3) & 1;
            MBAR_WAIT(sb + 8 + 8 * ws, wp2);   // MMA(c-2) done -> stage (c+1)%3 free
        }
        // A(c+1) straight into the swizzled tile via cp.async
        if (c + 1 < NC) {
            unsigned adst = sb + G2_A + ((c + 1) % 3) * STG;
            const __half* asrc = arow + (c + 1) * 64 + lh * 32;
            #pragma unroll
            for (int q = 0; q < 4; q++)
                cpa16(adst + swoff(bo + q * 16), asrc + q * 8);
        }
        CP_COMMIT();
        CP_WAIT(2);   // Bp(c) and A(c) complete; Bp(c+1), A(c+1) stay pending
        char* Bt = smem + G2_B + st * STG;
        int4 wd = *(const int4*)(smem + G2_PB + (c & 1) * 4096 + tid * 16);
        stage_B(Bt, wd, sd2, bo);
        if (c + 2 < NC)
            cpa16(sb + G2_PB + (c & 1) * 4096 + tid * 16, dpr + (c + 2) * 8);
        CP_COMMIT();
        FENCE_ASYNC();
        __syncthreads();
        if (tid == 0) {
            unsigned long long ad = make_desc(sb + G2_A + st * STG);
            unsigned long long bd = make_desc(sb + G2_B + st * STG);
            #pragma unroll
            for (int ks = 0; ks < 4; ks++) {
                unsigned en = (c > 0 || ks > 0) ? 1u : 0u;
                mma_f16_ss(tb, ad + ks * 2, bd + ks * 2, en);
            }
            TC_COMMIT(sb + 8 + 8 * st);
        }
        sd2 = sd2N;
    }
    {
        const int ls = (NC - 1) % 3;
        const int lp = (((NC - 1) - ls) / 3) & 1;
        MBAR_WAIT(sb + 8 + 8 * ls, lp);
    }
    TC_FENCE_AFTER();

    const int w4 = wid & 3, hf = wid >> 2;
    const int r = w4 * 32 + lid;
    bool valid = XP ? (r < nrows) : true;
    int tok = 0; float wgt = 0.f;
    if (XP) { if (valid) { tok = g_slotTok[e * C_ + r]; wgt = g_slotW[e * C_ + r]; } }
    else    { tok = m0 + r; wgt = 1.f; }
    #pragma unroll
    for (int b = 0; b < 2; b++) {
        int cb = hf * 64 + b * 32;
        unsigned dr[32];
        TC_LD32(dr, tb + cb);
        TC_WAIT_LD();
        if (valid) {
            float* dst = y + (size_t)tok * H_ + n0 + cb;
            #pragma unroll
            for (int j = 0; j < 32; j++)
                atomicAdd(dst + j, wgt * __uint_as_float(dr[j]));
        }
    }
    TC_FENCE_BEFORE();
    __syncthreads();
    if (tid == 0) { MBAR_INVAL(sb + 8); MBAR_INVAL(sb + 16); MBAR_INVAL(sb + 24); }
    __syncthreads();
    if (wid == 0) { TC_RELINQ(); TC_DEALLOC(tb, 128); }
}

#else  // !TC_OK
// ===========================================================================
// fallback: mma.sync.m16n8k16 (compiles for plain sm_103; not selected on GB300)
// ===========================================================================
__device__ __forceinline__ void ldm_x4(unsigned r[4], unsigned a) {
    asm volatile("ldmatrix.sync.aligned.m8n8.x4.shared.b16 {%0,%1,%2,%3}, [%4];"
                 : "=r"(r[0]), "=r"(r[1]), "=r"(r[2]), "=r"(r[3]) : "r"(a));
}
__device__ __forceinline__ void ldm_x2(unsigned r[2], unsigned a) {
    asm volatile("ldmatrix.sync.aligned.m8n8.x2.shared.b16 {%0,%1}, [%2];"
                 : "=r"(r[0]), "=r"(r[1]) : "r"(a));
}
__device__ __forceinline__ void mma16816(float* d, const unsigned* a, const unsigned* b) {
    asm volatile("mma.sync.aligned.m16n8k16.row.col.f32.f16.f16.f32 "
        "{%0,%1,%2,%3}, {%4,%5,%6,%7}, {%8,%9}, {%0,%1,%2,%3};"
        : "+f"(d[0]), "+f"(d[1]), "+f"(d[2]), "+f"(d[3])
        : "r"(a[0]), "r"(a[1]), "r"(a[2]), "r"(a[3]), "r"(b[0]), "r"(b[1]));
}

__global__ __launch_bounds__(256) void mma_gemm1(
    const float* __restrict__ x,
    const int* __restrict__ gp, const float* __restrict__ gsc,
    const int* __restrict__ up, const float* __restrict__ usc,
    const int* __restrict__ sgp, const float* __restrict__ sgs,
    const int* __restrict__ sup, const float* __restrict__ sus) {
    constexpr int NC = H_ / 64;
    extern __shared__ char smem[];
    const int tid = threadIdx.x, wid = tid >> 5, lane = tid & 31;
    const int j0 = blockIdx.x * 128;
    const int by = blockIdx.y;
    const bool XP = by < E_;
    const int e  = XP ? by : 0;
    const int m0 = XP ? 0 : (by - E_) * 128;
    const int nrows = XP ? g_cnt[e] : 128;
    if (nrows == 0) return;

    unsigned sb = smem_u32(smem);
    const unsigned Ab = sb + G1_A, Bgb = sb + G1_BG, Bub = sb + G1_BU;

    const int lrow = tid >> 1, lh = tid & 1;
    const float* arow = nullptr;
    if (XP) { if (lrow < nrows) arow = x + (size_t)g_slotTok[e * C_ + lrow] * H_; }
    else      arow = x + (size_t)(m0 + lrow) * H_;
    const size_t wr0 = ((size_t)(XP ? e * I_ : 0) + j0 + lrow) * (H_ / 8) + lh * 4;
    const int* gpr = (XP ? gp  : sgp) + wr0;
    const int* upr = (XP ? up  : sup) + wr0;
    const size_t sc0 = (size_t)(XP ? e * (H_ / GS_) * I_ : 0) + j0 + lrow;
    const float* gsp = (XP ? gsc : sgs) + sc0;
    const float* usp = (XP ? usc : sus) + sc0;
    const int bo = lrow * 128 + lh * 64;
    const int wm = wid >> 2, wn = wid & 3;

    float ag[4][4][4], au[4][4][4];
    #pragma unroll
    for (int i = 0; i < 4; i++)
        #pragma unroll
        for (int j = 0; j < 4; j++)
            #pragma unroll
            for (int q = 0; q < 4; q++) { ag[i][j][q] = 0.f; au[i][j][q] = 0.f; }

    for (int c = 0; c < NC; c++) {
        int kk = c * 64;
        if (arow) stage_A_f32(smem + G1_A, arow, kk, bo, lh);
        stage_B(smem + G1_BG, *(const int4*)(gpr + (kk >> 3)),
                pack_sc(gsp[(size_t)(kk >> 7) * I_]), bo);
        stage_B(smem + G1_BU, *(const int4*)(upr + (kk >> 3)),
                pack_sc(usp[(size_t)(kk >> 7) * I_]), bo);
        __syncthreads();
        #pragma unroll
        for (int ks = 0; ks < 4; ks++) {
            unsigned af[4][4];
            #pragma unroll
            for (int mt = 0; mt < 4; mt++)
                ldm_x4(af[mt], swadr(Ab, wm * 64 + mt * 16 + (lane & 15),
                                     ks * 32 + (lane >> 4) * 16));
            #pragma unroll
            for (int nt = 0; nt < 4; nt++) {
                int brow = wn * 32 + nt * 8 + (lane & 7);
                int bcol = ks * 32 + ((lane >> 3) & 1) * 16;
                unsigned bg[2], bu[2];
                ldm_x2(bg, swadr(Bgb, brow, bcol));
                ldm_x2(bu, swadr(Bub, brow, bcol));
                #pragma unroll
                for (int mt = 0; mt < 4; mt++) {
                    mma16816(ag[mt][nt], af[mt], bg);
                    mma16816(au[mt][nt], af[mt], bu);
                }
            }
        }
        __syncthreads();
    }
    const int g = lane >> 2, cq = lane & 3;
    #pragma unroll
    for (int mt = 0; mt < 4; mt++)
        #pragma unroll
        for (int nt = 0; nt < 4; nt++) {
            int nn = j0 + wn * 32 + nt * 8 + cq * 2;
            #pragma unroll
            for (int hrow = 0; hrow < 2; hrow++) {
                int r = wm * 64 + mt * 16 + g + hrow * 8;
                if (XP && r >= nrows) continue;
                float g0 = ag[mt][nt][hrow * 2], g1 = ag[mt][nt][hrow * 2 + 1];
                float u0 = au[mt][nt][hrow * 2], u1 = au[mt][nt][hrow * 2 + 1];
                float v0 = g0 / (1.f + expf(-g0)) * u0;
                float v1 = g1 / (1.f + expf(-g1)) * u1;
                __half* dst = (XP ? g_hbuf + ((size_t)e * C_ + r) * I_
                                  : g_hsh + (size_t)(m0 + r) * I_) + nn;
                *reinterpret_cast<__half2*>(dst) =
                    __float22half2_rn(make_float2(v0, v1));
            }
        }
}

__global__ __launch_bounds__(256) void mma_gemm2(
    const int* __restrict__ dp, const float* __restrict__ dsc,
    const int* __restrict__ sdp, const float* __restrict__ sds,
    float* __restrict__ y) {
    constexpr int NC = I_ / 64;
    extern __shared__ char smem[];
    const int tid = threadIdx.x, wid = tid >> 5, lane = tid & 31;
    const int n0 = blockIdx.x * 128;
    const int by = blockIdx.y;
    const bool XP = by < E_;
    const int e  = XP ? by : 0;
    const int m0 = XP ? 0 : (by - E_) * 128;
    const int nrows = XP ? g_cnt[e] : 128;
    if (nrows == 0) return;

    unsigned sb = smem_u32(smem);
    const unsigned Ab = sb + G2_A, Bb = sb + G2_B;

    const int lrow = tid >> 1, lh = tid & 1;
    const __half* arow = XP ? (g_hbuf + ((size_t)e * C_ + lrow) * I_)
                            : (g_hsh  + (size_t)(m0 + lrow) * I_);
    const int* dpr = (XP ? dp : sdp)
                   + ((size_t)(XP ? e * H_ : 0) + n0 + lrow) * (I_ / 8) + lh * 4;
    const float* dsp = (XP ? dsc : sds)
                     + (size_t)(XP ? e * (I_ / GS_) * H_ : 0) + n0 + lrow;
    const int bo = lrow * 128 + lh * 64;
    const int wm = wid >> 2, wn = wid & 3;

    float acc[4][4][4];
    #pragma unroll
    for (int i = 0; i < 4; i++)
        #pragma unroll
        for (int j = 0; j < 4; j++)
            #pragma unroll
            for (int q = 0; q < 4; q++) acc[i][j][q] = 0.f;

    for (int c = 0; c < NC; c++) {
        int kk = c * 64;
        stage_A_f16(smem + G2_A, arow, kk, bo, lh);
        stage_B(smem + G2_B, *(const int4*)(dpr + (kk >> 3)),
                pack_sc(dsp[(size_t)(kk >> 7) * H_]), bo);
        __syncthreads();
        #pragma unroll
        for (int ks = 0; ks < 4; ks++) {
            unsigned af[4][4];
            #pragma unroll
            for (int mt = 0; mt < 4; mt++)
                ldm_x4(af[mt], swadr(Ab, wm * 64 + mt * 16 + (lane & 15),
                                     ks * 32 + (lane >> 4) * 16));
            #pragma unroll
            for (int nt = 0; nt < 4; nt++) {
                int brow = wn * 32 + nt * 8 + (lane & 7);
                int bcol = ks * 32 + ((lane >> 3) & 1) * 16;
                unsigned bf[2];
                ldm_x2(bf, swadr(Bb, brow, bcol));
                #pragma unroll
                for (int mt = 0; mt < 4; mt++)
                    mma16816(acc[mt][nt], af[mt], bf);
            }
        }
        __syncthreads();
    }
    const int g = lane >> 2, cq = lane & 3;
    #pragma unroll
    for (int mt = 0; mt < 4; mt++)
        #pragma unroll
        for (int hrow = 0; hrow < 2; hrow++) {
            int r = wm * 64 + mt * 16 + g + hrow * 8;
            if (XP && r >= nrows) continue;
            int tok; float wgt;
            if (XP) { tok = g_slotTok[e * C_ + r]; wgt = g_slotW[e * C_ + r]; }
            else    { tok = m0 + r; wgt = 1.f; }
            #pragma unroll
            for (int nt = 0; nt < 4; nt++) {
                int nn = n0 + wn * 32 + nt * 8 + cq * 2;
                float* dst = y + (size_t)tok * H_ + nn;
                atomicAdd(dst,     wgt * acc[mt][nt][hrow * 2]);
                atomicAdd(dst + 1, wgt * acc[mt][nt][hrow * 2 + 1]);
            }
        }
}
#endif  // TC_OK

// ---------------------------------------------------------------------------
// launch
// ---------------------------------------------------------------------------
extern "C" void kernel_launch(void* const* d_in, const int* in_sizes, int n_in,
                              void* d_out, int out_size) {
    const float* x   = (const float*)d_in[0];
    const float* gw  = (const float*)d_in[1];
    const float* gsc = (const float*)d_in[2];
    const float* usc = (const float*)d_in[3];
    const float* dsc = (const float*)d_in[4];
    const float* sgs = (const float*)d_in[5];
    const float* sus = (const float*)d_in[6];
    const float* sds = (const float*)d_in[7];
    const int*   gpk = (const int*)d_in[8];
    const int*   upk = (const int*)d_in[9];
    const int*   dpk = (const int*)d_in[10];
    const int*   sgp = (const int*)d_in[11];
    const int*   sup = (const int*)d_in[12];
    const int*   sdp = (const int*)d_in[13];
    float* y = (float*)d_out;

    cudaFuncSetAttribute(mma_gemm1, cudaFuncAttributeMaxDynamicSharedMemorySize, SM1);
    cudaFuncSetAttribute(mma_gemm2, cudaFuncAttributeMaxDynamicSharedMemorySize, SM2);

    routing_kernel<<<T_ / 8, 256>>>(x, gw);
    dispatch_kernel<<<2, 1024>>>();
    zero_y_kernel<<<(T_ * H_ / 4) / 512, 512>>>((float4*)y);

    // stage 1: SwiGLU intermediates (experts y=0..63, shared tiles y=64..71)
    mma_gemm1<<<dim3(I_ / 128, E_ + T_ / 128), 256, SM1>>>(
        x, gpk, gsc, upk, usc, sgp, sgs, sup, sus);

    // stage 2: down-proj, all paths atomicAdd into zeroed y
    mma_gemm2<<<dim3(H_ / 128, E_ + T_ / 128), 256, SM2>>>(
        dpk, dsc, sdp, sds, y);
}

// round 7
// speedup vs baseline: 7.6089x; 1.2057x over previous
#include <cuda_runtime.h>
#include <cuda_fp16.h>
#include <math.h>

#define E_   64
#define KTOP 4
#define H_   2048
#define I_   1536
#define GS_  128
#define T_   1024
#define C_   128

#if defined(__CUDA_ARCH__) && !defined(__CUDA_ARCH_FEAT_SM103_ALL) && !defined(__CUDA_ARCH_FEAT_SM100_ALL)
#define TC_OK 0
#else
#define TC_OK 1
#endif

// ---------------------------------------------------------------------------
// common helpers
// ---------------------------------------------------------------------------
__device__ __forceinline__ unsigned smem_u32(const void* p) {
    unsigned a;
    asm("{ .reg .u64 t; cvta.to.shared.u64 t, %1; cvt.u32.u64 %0, t; }" : "=r"(a) : "l"(p));
    return a;
}
__device__ __forceinline__ unsigned h2u(__half2 h) {
    return *reinterpret_cast<unsigned*>(&h);
}
__device__ __forceinline__ unsigned swoff(int off) {
    return (unsigned)(off ^ ((off >> 3) & 0x70));
}
__device__ __forceinline__ void st_sw(char* base, int off, uint4 v) {
    *reinterpret_cast<uint4*>(base + swoff(off)) = v;
}
__device__ __forceinline__ unsigned swadr(unsigned base, int row, int col) {
    return base + swoff(row * 128 + col);
}
__device__ __forceinline__ unsigned pack_sc(float s) {
    return h2u(__float2half2_rn(s));
}

__device__ __forceinline__ void cpa16(unsigned dst, const void* src) {
    asm volatile("cp.async.ca.shared.global [%0], [%1], 16;" :: "r"(dst), "l"(src));
}
__device__ __forceinline__ void cpa8(unsigned dst, const void* src) {
    asm volatile("cp.async.ca.shared.global [%0], [%1], 8;" :: "r"(dst), "l"(src));
}
#define CP_COMMIT() asm volatile("cp.async.commit_group;" ::: "memory")
#define CP_WAIT(n)  asm volatile("cp.async.wait_group %0;" :: "n"(n) : "memory")

// FP4 E2M1 x8 -> 8 fp16 via PRMT tables; sc2 = half2(scale, scale)
__device__ __forceinline__ uint4 dec8p(unsigned w, unsigned sc2) {
    const unsigned tLo = 0x3E3C3800u, tHi = 0x46444240u;
    unsigned m0, m1;
    asm("prmt.b32 %0,%1,%2,%3;" : "=r"(m0) : "r"(tLo), "r"(tHi), "r"(w & 0x7777u));
    asm("prmt.b32 %0,%1,%2,%3;" : "=r"(m1) : "r"(tLo), "r"(tHi), "r"((w >> 16) & 0x7777u));
    unsigned q4 = (w << 4) & 0x80808080u;
    unsigned q0 = w & 0x80808080u;
    unsigned r[4];
    #pragma unroll
    for (int p = 0; p < 4; p++) {
        unsigned mag  = (p < 2) ? m0 : m1;
        unsigned mctl = (p & 1) ? 0x3424u : 0x1404u;
        unsigned me, se;
        asm("prmt.b32 %0,%1,%2,%3;" : "=r"(me) : "r"(mag), "r"(0u), "r"(mctl));
        unsigned sctl = 0x4000u + (unsigned)p * 0x1010u;
        asm("prmt.b32 %0,%1,%2,%3;" : "=r"(se) : "r"(q4), "r"(q0), "r"(sctl));
        unsigned v = me | (se & 0x80008000u);
        asm("mul.rn.f16x2 %0,%1,%2;" : "=r"(r[p]) : "r"(v), "r"(sc2));
    }
    return make_uint4(r[0], r[1], r[2], r[3]);
}

// fallback-path helpers (256-thread mappings)
__device__ __forceinline__ void stage_B4(char* Bt, int4 w, unsigned sc2, int bo) {
    st_sw(Bt, bo + 0,  dec8p((unsigned)w.x, sc2));
    st_sw(Bt, bo + 16, dec8p((unsigned)w.y, sc2));
    st_sw(Bt, bo + 32, dec8p((unsigned)w.z, sc2));
    st_sw(Bt, bo + 48, dec8p((unsigned)w.w, sc2));
}
__device__ __forceinline__ void stage_A_f32(char* At, const float* arow, int kk,
                                            int bo, int lh) {
    #pragma unroll
    for (int q = 0; q < 4; q++) {
        const float* p = arow + kk + lh * 32 + q * 8;
        float4 fa = *(const float4*)p;
        float4 fb = *(const float4*)(p + 4);
        uint4 v;
        v.x = h2u(__float22half2_rn(make_float2(fa.x, fa.y)));
        v.y = h2u(__float22half2_rn(make_float2(fa.z, fa.w)));
        v.z = h2u(__float22half2_rn(make_float2(fb.x, fb.y)));
        v.w = h2u(__float22half2_rn(make_float2(fb.z, fb.w)));
        st_sw(At, bo + q * 16, v);
    }
}
__device__ __forceinline__ void stage_A_f16(char* At, const __half* arow, int kk,
                                            int bo, int lh) {
    #pragma unroll
    for (int q = 0; q < 4; q++) {
        uint4 v = *reinterpret_cast<const uint4*>(arow + kk + lh * 32 + q * 8);
        st_sw(At, bo + q * 16, v);
    }
}

// ---------------------------------------------------------------------------
// scratch
// ---------------------------------------------------------------------------
__device__ int    g_ti[T_ * KTOP];
__device__ float  g_tw[T_ * KTOP];
__device__ int    g_cnt[E_];
__device__ int    g_slotTok[E_ * C_];
__device__ float  g_slotW[E_ * C_];
__device__ __half g_hbuf[(size_t)E_ * C_ * I_];
__device__ __half g_hsh[(size_t)T_ * I_];
__device__ __half g_xh[(size_t)T_ * H_];

// ---------------------------------------------------------------------------
// routing + dispatch + zero + xcvt
// ---------------------------------------------------------------------------
__global__ void routing_kernel(const float* __restrict__ x,
                               const float* __restrict__ gw) {
    __shared__ float lg[8][E_];
    int tid  = threadIdx.x;
    int tok0 = blockIdx.x * 8;
    #pragma unroll
    for (int p = 0; p < 2; p++) {
        int pair = tid + p * 256;
        int tk = pair >> 6, e = pair & 63;
        const float* xr = x  + (size_t)(tok0 + tk) * H_;
        const float* wr = gw + (size_t)e * H_;
        float acc = 0.f;
        for (int h = 0; h < H_; h += 4) {
            float4 a = *(const float4*)(xr + h);
            float4 b = *(const float4*)(wr + h);
            acc += a.x * b.x + a.y * b.y + a.z * b.z + a.w * b.w;
        }
        lg[tk][e] = acc;
    }
    __syncthreads();
    if (tid < 8) {
        int t = tok0 + tid;
        unsigned long long used = 0ull;
        float v[KTOP]; int id[KTOP];
        #pragma unroll
        for (int k = 0; k < KTOP; k++) {
            float best = -INFINITY; int bi = 0;
            for (int e = 0; e < E_; e++)
                if (!((used >> e) & 1ull) && lg[tid][e] > best) { best = lg[tid][e]; bi = e; }
            v[k] = best; id[k] = bi; used |= 1ull << bi;
        }
        float mx = v[0], w[KTOP], sum = 0.f;
        #pragma unroll
        for (int k = 0; k < KTOP; k++) { w[k] = expf(v[k] - mx); sum += w[k]; }
        #pragma unroll
        for (int k = 0; k < KTOP; k++) {
            g_ti[t * KTOP + k] = id[k];
            g_tw[t * KTOP + k] = w[k] / sum;
        }
    }
}

__global__ void dispatch_kernel() {
    __shared__ int sti[T_ * KTOP];
    int tid = threadIdx.x;
    for (int i = tid; i < T_ * KTOP; i += blockDim.x) sti[i] = g_ti[i];
    __syncthreads();
    int wid = tid >> 5, lane = tid & 31;
    int e = blockIdx.x * (blockDim.x >> 5) + wid;
    if (e < E_) {
        int cnt = 0;
        for (int base = 0; base < T_ * KTOP; base += 32) {
            int a = base + lane;
            bool m = (sti[a] == e);
            unsigned msk = __ballot_sync(0xffffffffu, m);
            if (m) {
                int c = cnt + __popc(msk & ((1u << lane) - 1u));
                if (c < C_) {
                    g_slotTok[e * C_ + c] = a >> 2;
                    g_slotW[e * C_ + c]   = g_tw[a];
                }
            }
            cnt += __popc(msk);
        }
        if (lane == 0) g_cnt[e] = cnt < C_ ? cnt : C_;
    }
}

__global__ void zero_y_kernel(float4* y) {
    y[(size_t)blockIdx.x * blockDim.x + threadIdx.x] = make_float4(0.f, 0.f, 0.f, 0.f);
}

__global__ void xcvt_kernel(const float4* __restrict__ x) {
    size_t i = (size_t)blockIdx.x * blockDim.x + threadIdx.x;
    float4 v = x[i];
    uint2 o;
    o.x = h2u(__float22half2_rn(make_float2(v.x, v.y)));
    o.y = h2u(__float22half2_rn(make_float2(v.z, v.w)));
    reinterpret_cast<uint2*>(g_xh)[i] = o;
}

// SMEM layouts (audited: disjoint, tiles 1024-aligned)
// gemm1: hdr[0,64) | PG 2x4096 [64,8256) | PU 2x4096 [8256,16448)
//        | A 3x16K @17408 | Bg 3x16K @66560 | Bu 3x16K @115712 | end 164864
#define G1_PG  64
#define G1_PU  8256
#define G1_A   17408
#define G1_BG  66560
#define G1_BU  115712
#define SM1    164864
// gemm2: hdr[0,64) | PB 2x4096 [64,8256) | A 3x16K @16384 | B 3x16K @65536
#define G2_PB  64
#define G2_A   16384
#define G2_B   65536
#define SM2    114688
#define STG    16384

#if TC_OK
// ===========================================================================
// tcgen05 path
// ===========================================================================
#define TC_ALLOC(sm, n)  asm volatile("tcgen05.alloc.cta_group::1.sync.aligned.shared::cta.b32 [%0], %1;" :: "r"(sm), "r"(n) : "memory")
#define TC_DEALLOC(tb,n) asm volatile("tcgen05.dealloc.cta_group::1.sync.aligned.b32 %0, %1;" :: "r"(tb), "r"(n))
#define TC_RELINQ()      asm volatile("tcgen05.relinquish_alloc_permit.cta_group::1.sync.aligned;")
#define TC_COMMIT(bar)   asm volatile("tcgen05.commit.cta_group::1.mbarrier::arrive::one.shared::cluster.b64 [%0];" :: "r"(bar) : "memory")
#define TC_FENCE_AFTER()  asm volatile("tcgen05.fence::after_thread_sync;" ::: "memory")
#define TC_FENCE_BEFORE() asm volatile("tcgen05.fence::before_thread_sync;" ::: "memory")
#define TC_WAIT_LD()      asm volatile("tcgen05.wait::ld.sync.aligned;" ::: "memory")
#define FENCE_ASYNC()     asm volatile("fence.proxy.async.shared::cta;" ::: "memory")
#define MBAR_INIT(a, c)  asm volatile("mbarrier.init.shared.b64 [%0], %1;" :: "r"(a), "r"(c) : "memory")
#define MBAR_INVAL(a)    asm volatile("mbarrier.inval.shared.b64 [%0];" :: "r"(a) : "memory")

#define MBAR_WAIT(addr, par) do {                                              \
    unsigned _m = (unsigned)(addr), _p = (unsigned)(par), _d;                  \
    asm volatile("{\n\t.reg .pred p;\n\t"                                      \
        "mbarrier.try_wait.parity.acquire.cta.shared::cta.b64 p, [%1], %2;\n\t"\
        "selp.b32 %0,1,0,p;\n\t}" : "=r"(_d) : "r"(_m), "r"(_p) : "memory");   \
    if (!_d) {                                                                 \
        asm volatile("{\n\t.reg .pred P1;\n\t"                                 \
        "WL_%=:\n\t"                                                           \
        "mbarrier.try_wait.parity.acquire.cta.shared::cta.b64 P1, [%0], %1, 0x989680;\n\t" \
        "@P1 bra.uni WD_%=;\n\t"                                               \
        "bra.uni WL_%=;\n\t"                                                   \
        "WD_%=:\n\t}" :: "r"(_m), "r"(_p) : "memory");                         \
    }                                                                          \
} while (0)

#define TC_LD32(r, ta) \
    asm volatile( \
        "tcgen05.ld.sync.aligned.32x32b.x32.b32 " \
        "{%0, %1, %2, %3, %4, %5, %6, %7, " \
        " %8, %9, %10, %11, %12, %13, %14, %15, " \
        " %16, %17, %18, %19, %20, %21, %22, %23, " \
        " %24, %25, %26, %27, %28, %29, %30, %31}, [%32];" \
        : "=r"((r)[0]),  "=r"((r)[1]),  "=r"((r)[2]),  "=r"((r)[3]), \
          "=r"((r)[4]),  "=r"((r)[5]),  "=r"((r)[6]),  "=r"((r)[7]), \
          "=r"((r)[8]),  "=r"((r)[9]),  "=r"((r)[10]), "=r"((r)[11]), \
          "=r"((r)[12]), "=r"((r)[13]), "=r"((r)[14]), "=r"((r)[15]), \
          "=r"((r)[16]), "=r"((r)[17]), "=r"((r)[18]), "=r"((r)[19]), \
          "=r"((r)[20]), "=r"((r)[21]), "=r"((r)[22]), "=r"((r)[23]), \
          "=r"((r)[24]), "=r"((r)[25]), "=r"((r)[26]), "=r"((r)[27]), \
          "=r"((r)[28]), "=r"((r)[29]), "=r"((r)[30]), "=r"((r)[31]) \
        : "r"(ta))

#define IDESC_F16 ((1u << 4) | (16u << 17) | (8u << 24))

__device__ __forceinline__ void mma_f16_ss(unsigned d, unsigned long long a,
                                           unsigned long long b, unsigned en) {
    asm volatile("{\n\t.reg .pred p;\n\tsetp.ne.u32 p, %4, 0;\n\t"
        "tcgen05.mma.cta_group::1.kind::f16 [%0], %1, %2, %3, {%5,%5,%5,%5}, p;\n\t}"
        :: "r"(d), "l"(a), "l"(b), "r"(IDESC_F16), "r"(en), "r"(0u) : "memory");
}
__device__ __forceinline__ unsigned long long make_desc(unsigned addr) {
    return ((unsigned long long)2 << 61) | ((unsigned long long)1 << 46)
         | ((unsigned long long)64 << 32) | ((unsigned long long)1 << 16)
         | ((addr >> 4) & 0x3FFFu);
}

__global__ __launch_bounds__(512) void mma_gemm1(
    const float* __restrict__ x,
    const int* __restrict__ gp, const float* __restrict__ gsc,
    const int* __restrict__ up, const float* __restrict__ usc,
    const int* __restrict__ sgp, const float* __restrict__ sgs,
    const int* __restrict__ sup, const float* __restrict__ sus) {
    constexpr int NC = H_ / 64;   // 32
    extern __shared__ char smem[];
    const int tid = threadIdx.x, wid = tid >> 5, lid = tid & 31;
    const int j0 = blockIdx.x * 128;
    const int by = blockIdx.y;
    const bool XP = by < E_;
    const int e  = XP ? by : 0;
    const int m0 = XP ? 0 : (by - E_) * 128;
    const int nrows = XP ? g_cnt[e] : 128;
    if (nrows == 0) return;

    unsigned sb = smem_u32(smem);
    if (wid == 0) TC_ALLOC(sb, 256);
    if (tid == 0) { MBAR_INIT(sb + 8, 1); MBAR_INIT(sb + 16, 1); MBAR_INIT(sb + 24, 1); }
    __syncthreads();
    unsigned tb;
    asm("ld.shared.b32 %0, [%1];" : "=r"(tb) : "r"(sb));

    const int lrow = tid >> 2, lq = tid & 3;
    const __half* arow;
    if (XP) {
        int tok = (lrow < nrows) ? g_slotTok[e * C_ + lrow] : 0;
        arow = g_xh + (size_t)tok * H_;
    } else {
        arow = g_xh + (size_t)(m0 + lrow) * H_;
    }
    const size_t wr0 = ((size_t)(XP ? e * I_ : 0) + j0 + lrow) * (H_ / 8) + lq * 2;
    const int* gpr = (XP ? gp : sgp) + wr0;
    const int* upr = (XP ? up : sup) + wr0;
    const size_t sc0 = (size_t)(XP ? e * (H_ / GS_) * I_ : 0) + j0 + lrow;
    const float* gsp = (XP ? gsc : sgs) + sc0;
    const float* usp = (XP ? usc : sus) + sc0;
    const int bo = lrow * 128 + lq * 32;
    const __half* asrc0 = arow + lq * 16;

    // prologue: B(0) slot0; A(0) stage0; B(1) slot1   (FIFO order matters)
    cpa8(sb + G1_PG + tid * 8, gpr);
    cpa8(sb + G1_PU + tid * 8, upr);
    CP_COMMIT();
    cpa16(sb + G1_A + swoff(bo),      asrc0);
    cpa16(sb + G1_A + swoff(bo + 16), asrc0 + 8);
    CP_COMMIT();
    cpa8(sb + G1_PG + 4096 + tid * 8, gpr + 8);
    cpa8(sb + G1_PU + 4096 + tid * 8, upr + 8);
    CP_COMMIT();
    unsigned sg2 = pack_sc(gsp[0]), su2 = pack_sc(usp[0]);

    for (int c = 0; c < NC; c++) {
        const int st = c % 3;
        unsigned sg2N = sg2, su2N = su2;
        if (c + 1 < NC) {
            sg2N = pack_sc(gsp[(size_t)((c + 1) >> 1) * I_]);
            su2N = pack_sc(usp[(size_t)((c + 1) >> 1) * I_]);
        }
        if (c >= 2) {
            int ws = (c - 2) % 3, wp2 = ((c - 2) / 3) & 1;
            MBAR_WAIT(sb + 8 + 8 * ws, wp2);    // MMA(c-2) done -> stage (c+1)%3 free
        }
        // A(c+1) straight into the swizzled tile
        if (c + 1 < NC) {
            unsigned adst = sb + G1_A + ((c + 1) % 3) * STG;
            const __half* asrc = asrc0 + (c + 1) * 64;
            cpa16(adst + swoff(bo),      asrc);
            cpa16(adst + swoff(bo + 16), asrc + 8);
        }
        CP_COMMIT();
        CP_WAIT(2);   // B(c) and A(c) landed
        int2 wg = *(const int2*)(smem + G1_PG + (c & 1) * 4096 + tid * 8);
        int2 wu = *(const int2*)(smem + G1_PU + (c & 1) * 4096 + tid * 8);
        char* Bg = smem + G1_BG + st * STG;
        char* Bu = smem + G1_BU + st * STG;
        st_sw(Bg, bo + 0,  dec8p((unsigned)wg.x, sg2));
        st_sw(Bg, bo + 16, dec8p((unsigned)wg.y, sg2));
        st_sw(Bu, bo + 0,  dec8p((unsigned)wu.x, su2));
        st_sw(Bu, bo + 16, dec8p((unsigned)wu.y, su2));
        if (c + 2 < NC) {
            cpa8(sb + G1_PG + (c & 1) * 4096 + tid * 8, gpr + (c + 2) * 8);
            cpa8(sb + G1_PU + (c & 1) * 4096 + tid * 8, upr + (c + 2) * 8);
        }
        CP_COMMIT();
        FENCE_ASYNC();
        __syncthreads();
        if (tid == 0) {
            unsigned long long ad = make_desc(sb + G1_A  + st * STG);
            unsigned long long gd = make_desc(sb + G1_BG + st * STG);
            unsigned long long ud = make_desc(sb + G1_BU + st * STG);
            #pragma unroll
            for (int ks = 0; ks < 4; ks++) {
                unsigned en = (c > 0 || ks > 0) ? 1u : 0u;
                mma_f16_ss(tb,       ad + ks * 2, gd + ks * 2, en);
                mma_f16_ss(tb + 128, ad + ks * 2, ud + ks * 2, en);
            }
            TC_COMMIT(sb + 8 + 8 * st);
        }
        sg2 = sg2N; su2 = su2N;
    }
    {
        const int ls = (NC - 1) % 3;
        MBAR_WAIT(sb + 8 + 8 * ls, (((NC - 1) - ls) / 3) & 1);
    }
    TC_FENCE_AFTER();

    // epilogue: 16 warps, warp = (rowgrp = wid&3, colblk = wid>>2)
    const int r = (wid & 3) * 32 + lid;
    const int cb = (wid >> 2) * 32;
    bool valid = XP ? (r < nrows) : true;
    __half* drow = XP ? (g_hbuf + ((size_t)e * C_ + r) * I_)
                      : (g_hsh  + (size_t)(m0 + r) * I_);
    unsigned gr[32], ur[32];
    TC_LD32(gr, tb + cb);
    TC_LD32(ur, tb + 128 + cb);
    TC_WAIT_LD();
    if (valid) {
        #pragma unroll
        for (int q = 0; q < 4; q++) {
            float v[8];
            #pragma unroll
            for (int t = 0; t < 8; t++) {
                int j = q * 8 + t;
                float gv = __uint_as_float(gr[j]);
                float uv = __uint_as_float(ur[j]);
                v[t] = gv / (1.f + __expf(-gv)) * uv;
            }
            uint4 o;
            o.x = h2u(__float22half2_rn(make_float2(v[0], v[1])));
            o.y = h2u(__float22half2_rn(make_float2(v[2], v[3])));
            o.z = h2u(__float22half2_rn(make_float2(v[4], v[5])));
            o.w = h2u(__float22half2_rn(make_float2(v[6], v[7])));
            *reinterpret_cast<uint4*>(drow + j0 + cb + q * 8) = o;
        }
    }
    TC_FENCE_BEFORE();
    __syncthreads();
    if (tid == 0) { MBAR_INVAL(sb + 8); MBAR_INVAL(sb + 16); MBAR_INVAL(sb + 24); }
    __syncthreads();
    if (wid == 0) { TC_RELINQ(); TC_DEALLOC(tb, 256); }
}

__global__ __launch_bounds__(512) void mma_gemm2(
    const int* __restrict__ dp, const float* __restrict__ dsc,
    const int* __restrict__ sdp, const float* __restrict__ sds,
    float* __restrict__ y) {
    constexpr int NC = I_ / 64;   // 24
    extern __shared__ char smem[];
    const int tid = threadIdx.x, wid = tid >> 5, lid = tid & 31;
    const int n0 = blockIdx.x * 128;
    const int by = blockIdx.y;
    const bool XP = by < E_;
    const int e  = XP ? by : 0;
    const int m0 = XP ? 0 : (by - E_) * 128;
    const int nrows = XP ? g_cnt[e] : 128;
    if (nrows == 0) return;

    unsigned sb = smem_u32(smem);
    if (wid == 0) TC_ALLOC(sb, 128);
    if (tid == 0) { MBAR_INIT(sb + 8, 1); MBAR_INIT(sb + 16, 1); MBAR_INIT(sb + 24, 1); }
    __syncthreads();
    unsigned tb;
    asm("ld.shared.b32 %0, [%1];" : "=r"(tb) : "r"(sb));

    const int lrow = tid >> 2, lq = tid & 3;
    const __half* arow = XP ? (g_hbuf + ((size_t)e * C_ + lrow) * I_)
                            : (g_hsh  + (size_t)(m0 + lrow) * I_);
    const int* dpr = (XP ? dp : sdp)
                   + ((size_t)(XP ? e * H_ : 0) + n0 + lrow) * (I_ / 8) + lq * 2;
    const float* dsp = (XP ? dsc : sds)
                     + (size_t)(XP ? e * (I_ / GS_) * H_ : 0) + n0 + lrow;
    const int bo = lrow * 128 + lq * 32;
    const __half* asrc0 = arow + lq * 16;

    // prologue: Bp(0); A(0)->stage0; Bp(1)
    cpa8(sb + G2_PB + tid * 8, dpr);
    CP_COMMIT();
    cpa16(sb + G2_A + swoff(bo),      asrc0);
    cpa16(sb + G2_A + swoff(bo + 16), asrc0 + 8);
    CP_COMMIT();
    cpa8(sb + G2_PB + 4096 + tid * 8, dpr + 8);
    CP_COMMIT();
    unsigned sd2 = pack_sc(dsp[0]);

    for (int c = 0; c < NC; c++) {
        const int st = c % 3;
        unsigned sd2N = sd2;
        if (c + 1 < NC) sd2N = pack_sc(dsp[(size_t)((c + 1) >> 1) * H_]);
        if (c >= 2) {
            int ws = (c - 2) % 3, wp2 = ((c - 2) / 3) & 1;
            MBAR_WAIT(sb + 8 + 8 * ws, wp2);
        }
        if (c + 1 < NC) {
            unsigned adst = sb + G2_A + ((c + 1) % 3) * STG;
            const __half* asrc = asrc0 + (c + 1) * 64;
            cpa16(adst + swoff(bo),      asrc);
            cpa16(adst + swoff(bo + 16), asrc + 8);
        }
        CP_COMMIT();
        CP_WAIT(2);
        int2 wd = *(const int2*)(smem + G2_PB + (c & 1) * 4096 + tid * 8);
        char* Bt = smem + G2_B + st * STG;
        st_sw(Bt, bo + 0,  dec8p((unsigned)wd.x, sd2));
        st_sw(Bt, bo + 16, dec8p((unsigned)wd.y, sd2));
        if (c + 2 < NC)
            cpa8(sb + G2_PB + (c & 1) * 4096 + tid * 8, dpr + (c + 2) * 8);
        CP_COMMIT();
        FENCE_ASYNC();
        __syncthreads();
        if (tid == 0) {
            unsigned long long ad = make_desc(sb + G2_A + st * STG);
            unsigned long long bd = make_desc(sb + G2_B + st * STG);
            #pragma unroll
            for (int ks = 0; ks < 4; ks++) {
                unsigned en = (c > 0 || ks > 0) ? 1u : 0u;
                mma_f16_ss(tb, ad + ks * 2, bd + ks * 2, en);
            }
            TC_COMMIT(sb + 8 + 8 * st);
        }
        sd2 = sd2N;
    }
    {
        const int ls = (NC - 1) % 3;
        MBAR_WAIT(sb + 8 + 8 * ls, (((NC - 1) - ls) / 3) & 1);
    }
    TC_FENCE_AFTER();

    const int r = (wid & 3) * 32 + lid;
    const int cb = (wid >> 2) * 32;
    bool valid = XP ? (r < nrows) : true;
    int tok = 0; float wgt = 0.f;
    if (XP) { if (valid) { tok = g_slotTok[e * C_ + r]; wgt = g_slotW[e * C_ + r]; } }
    else    { tok = m0 + r; wgt = 1.f; }
    unsigned dr[32];
    TC_LD32(dr, tb + cb);
    TC_WAIT_LD();
    if (valid) {
        float* dst = y + (size_t)tok * H_ + n0 + cb;
        #pragma unroll
        for (int j = 0; j < 32; j++)
            atomicAdd(dst + j, wgt * __uint_as_float(dr[j]));
    }
    TC_FENCE_BEFORE();
    __syncthreads();
    if (tid == 0) { MBAR_INVAL(sb + 8); MBAR_INVAL(sb + 16); MBAR_INVAL(sb + 24); }
    __syncthreads();
    if (wid == 0) { TC_RELINQ(); TC_DEALLOC(tb, 128); }
}

#else  // !TC_OK
// ===========================================================================
// fallback: mma.sync (compiles for plain sm_103; never selected on GB300 —
// first 256 threads do the work, syncs stay block-wide)
// ===========================================================================
__device__ __forceinline__ void ldm_x4(unsigned r[4], unsigned a) {
    asm volatile("ldmatrix.sync.aligned.m8n8.x4.shared.b16 {%0,%1,%2,%3}, [%4];"
                 : "=r"(r[0]), "=r"(r[1]), "=r"(r[2]), "=r"(r[3]) : "r"(a));
}
__device__ __forceinline__ void ldm_x2(unsigned r[2], unsigned a) {
    asm volatile("ldmatrix.sync.aligned.m8n8.x2.shared.b16 {%0,%1}, [%2];"
                 : "=r"(r[0]), "=r"(r[1]) : "r"(a));
}
__device__ __forceinline__ void mma16816(float* d, const unsigned* a, const unsigned* b) {
    asm volatile("mma.sync.aligned.m16n8k16.row.col.f32.f16.f16.f32 "
        "{%0,%1,%2,%3}, {%4,%5,%6,%7}, {%8,%9}, {%0,%1,%2,%3};"
        : "+f"(d[0]), "+f"(d[1]), "+f"(d[2]), "+f"(d[3])
        : "r"(a[0]), "r"(a[1]), "r"(a[2]), "r"(a[3]), "r"(b[0]), "r"(b[1]));
}

__global__ __launch_bounds__(512) void mma_gemm1(
    const float* __restrict__ x,
    const int* __restrict__ gp, const float* __restrict__ gsc,
    const int* __restrict__ up, const float* __restrict__ usc,
    const int* __restrict__ sgp, const float* __restrict__ sgs,
    const int* __restrict__ sup, const float* __restrict__ sus) {
    constexpr int NC = H_ / 64;
    extern __shared__ char smem[];
    const int tid = threadIdx.x;
    const bool act = tid < 256;
    const int t2 = tid & 255, wid = t2 >> 5, lane = t2 & 31;
    const int j0 = blockIdx.x * 128;
    const int by = blockIdx.y;
    const bool XP = by < E_;
    const int e  = XP ? by : 0;
    const int m0 = XP ? 0 : (by - E_) * 128;
    const int nrows = XP ? g_cnt[e] : 128;
    if (nrows == 0) return;

    unsigned sb = smem_u32(smem);
    const unsigned Ab = sb + G1_A, Bgb = sb + G1_BG, Bub = sb + G1_BU;
    const int lrow = t2 >> 1, lh = t2 & 1;
    const float* arow = nullptr;
    if (XP) { if (lrow < nrows) arow = x + (size_t)g_slotTok[e * C_ + lrow] * H_; }
    else      arow = x + (size_t)(m0 + lrow) * H_;
    const size_t wr0 = ((size_t)(XP ? e * I_ : 0) + j0 + lrow) * (H_ / 8) + lh * 4;
    const int* gpr = (XP ? gp : sgp) + wr0;
    const int* upr = (XP ? up : sup) + wr0;
    const size_t sc0 = (size_t)(XP ? e * (H_ / GS_) * I_ : 0) + j0 + lrow;
    const float* gsp = (XP ? gsc : sgs) + sc0;
    const float* usp = (XP ? usc : sus) + sc0;
    const int bo = lrow * 128 + lh * 64;
    const int wm = wid >> 2, wn = wid & 3;

    float ag[4][4][4], au[4][4][4];
    #pragma unroll
    for (int i = 0; i < 4; i++)
        #pragma unroll
        for (int j = 0; j < 4; j++)
            #pragma unroll
            for (int q = 0; q < 4; q++) { ag[i][j][q] = 0.f; au[i][j][q] = 0.f; }

    for (int c = 0; c < NC; c++) {
        int kk = c * 64;
        if (act) {
            if (arow) stage_A_f32(smem + G1_A, arow, kk, bo, lh);
            stage_B4(smem + G1_BG, *(const int4*)(gpr + (kk >> 3)),
                     pack_sc(gsp[(size_t)(kk >> 7) * I_]), bo);
            stage_B4(smem + G1_BU, *(const int4*)(upr + (kk >> 3)),
                     pack_sc(usp[(size_t)(kk >> 7) * I_]), bo);
        }
        __syncthreads();
        if (act) {
            #pragma unroll
            for (int ks = 0; ks < 4; ks++) {
                unsigned af[4][4];
                #pragma unroll
                for (int mt = 0; mt < 4; mt++)
                    ldm_x4(af[mt], swadr(Ab, wm * 64 + mt * 16 + (lane & 15),
                                         ks * 32 + (lane >> 4) * 16));
                #pragma unroll
                for (int nt = 0; nt < 4; nt++) {
                    int brow = wn * 32 + nt * 8 + (lane & 7);
                    int bcol = ks * 32 + ((lane >> 3) & 1) * 16;
                    unsigned bg[2], bu[2];
                    ldm_x2(bg, swadr(Bgb, brow, bcol));
                    ldm_x2(bu, swadr(Bub, brow, bcol));
                    #pragma unroll
                    for (int mt = 0; mt < 4; mt++) {
                        mma16816(ag[mt][nt], af[mt], bg);
                        mma16816(au[mt][nt], af[mt], bu);
                    }
                }
            }
        }
        __syncthreads();
    }
    if (act) {
        const int g = lane >> 2, cq = lane & 3;
        #pragma unroll
        for (int mt = 0; mt < 4; mt++)
            #pragma unroll
            for (int nt = 0; nt < 4; nt++) {
                int nn = j0 + wn * 32 + nt * 8 + cq * 2;
                #pragma unroll
                for (int hrow = 0; hrow < 2; hrow++) {
                    int r = wm * 64 + mt * 16 + g + hrow * 8;
                    if (XP && r >= nrows) continue;
                    float g0 = ag[mt][nt][hrow * 2], g1 = ag[mt][nt][hrow * 2 + 1];
                    float u0 = au[mt][nt][hrow * 2], u1 = au[mt][nt][hrow * 2 + 1];
                    float v0 = g0 / (1.f + expf(-g0)) * u0;
                    float v1 = g1 / (1.f + expf(-g1)) * u1;
                    __half* dst = (XP ? g_hbuf + ((size_t)e * C_ + r) * I_
                                      : g_hsh + (size_t)(m0 + r) * I_) + nn;
                    *reinterpret_cast<__half2*>(dst) =
                        __float22half2_rn(make_float2(v0, v1));
                }
            }
    }
}

__global__ __launch_bounds__(512) void mma_gemm2(
    const int* __restrict__ dp, const float* __restrict__ dsc,
    const int* __restrict__ sdp, const float* __restrict__ sds,
    float* __restrict__ y) {
    constexpr int NC = I_ / 64;
    extern __shared__ char smem[];
    const int tid = threadIdx.x;
    const bool act = tid < 256;
    const int t2 = tid & 255, wid = t2 >> 5, lane = t2 & 31;
    const int n0 = blockIdx.x * 128;
    const int by = blockIdx.y;
    const bool XP = by < E_;
    const int e  = XP ? by : 0;
    const int m0 = XP ? 0 : (by - E_) * 128;
    const int nrows = XP ? g_cnt[e] : 128;
    if (nrows == 0) return;

    unsigned sb = smem_u32(smem);
    const unsigned Ab = sb + G2_A, Bb = sb + G2_B;
    const int lrow = t2 >> 1, lh = t2 & 1;
    const __half* arow = XP ? (g_hbuf + ((size_t)e * C_ + lrow) * I_)
                            : (g_hsh  + (size_t)(m0 + lrow) * I_);
    const int* dpr = (XP ? dp : sdp)
                   + ((size_t)(XP ? e * H_ : 0) + n0 + lrow) * (I_ / 8) + lh * 4;
    const float* dsp = (XP ? dsc : sds)
                     + (size_t)(XP ? e * (I_ / GS_) * H_ : 0) + n0 + lrow;
    const int bo = lrow * 128 + lh * 64;
    const int wm = wid >> 2, wn = wid & 3;

    float acc[4][4][4];
    #pragma unroll
    for (int i = 0; i < 4; i++)
        #pragma unroll
        for (int j = 0; j < 4; j++)
            #pragma unroll
            for (int q = 0; q < 4; q++) acc[i][j][q] = 0.f;

    for (int c = 0; c < NC; c++) {
        int kk = c * 64;
        if (act) {
            stage_A_f16(smem + G2_A, arow, kk, bo, lh);
            stage_B4(smem + G2_B, *(const int4*)(dpr + (kk >> 3)),
                     pack_sc(dsp[(size_t)(kk >> 7) * H_]), bo);
        }
        __syncthreads();
        if (act) {
            #pragma unroll
            for (int ks = 0; ks < 4; ks++) {
                unsigned af[4][4];
                #pragma unroll
                for (int mt = 0; mt < 4; mt++)
                    ldm_x4(af[mt], swadr(Ab, wm * 64 + mt * 16 + (lane & 15),
                                         ks * 32 + (lane >> 4) * 16));
                #pragma unroll
                for (int nt = 0; nt < 4; nt++) {
                    int brow = wn * 32 + nt * 8 + (lane & 7);
                    int bcol = ks * 32 + ((lane >> 3) & 1) * 16;
                    unsigned bf[2];
                    ldm_x2(bf, swadr(Bb, brow, bcol));
                    #pragma unroll
                    for (int mt = 0; mt < 4; mt++)
                        mma16816(acc[mt][nt], af[mt], bf);
                }
            }
        }
        __syncthreads();
    }
    if (act) {
        const int g = lane >> 2, cq = lane & 3;
        #pragma unroll
        for (int mt = 0; mt < 4; mt++)
            #pragma unroll
            for (int hrow = 0; hrow < 2; hrow++) {
                int r = wm * 64 + mt * 16 + g + hrow * 8;
                if (XP && r >= nrows) continue;
                int tok; float wgt;
                if (XP) { tok = g_slotTok[e * C_ + r]; wgt = g_slotW[e * C_ + r]; }
                else    { tok = m0 + r; wgt = 1.f; }
                #pragma unroll
                for (int nt = 0; nt < 4; nt++) {
                    int nn = n0 + wn * 32 + nt * 8 + cq * 2;
                    float* dst = y + (size_t)tok * H_ + nn;
                    atomicAdd(dst,     wgt * acc[mt][nt][hrow * 2]);
                    atomicAdd(dst + 1, wgt * acc[mt][nt][hrow * 2 + 1]);
                }
            }
    }
}
#endif  // TC_OK

// ---------------------------------------------------------------------------
// launch
// ---------------------------------------------------------------------------
extern "C" void kernel_launch(void* const* d_in, const int* in_sizes, int n_in,
                              void* d_out, int out_size) {
    const float* x   = (const float*)d_in[0];
    const float* gw  = (const float*)d_in[1];
    const float* gsc = (const float*)d_in[2];
    const float* usc = (const float*)d_in[3];
    const float* dsc = (const float*)d_in[4];
    const float* sgs = (const float*)d_in[5];
    const float* sus = (const float*)d_in[6];
    const float* sds = (const float*)d_in[7];
    const int*   gpk = (const int*)d_in[8];
    const int*   upk = (const int*)d_in[9];
    const int*   dpk = (const int*)d_in[10];
    const int*   sgp = (const int*)d_in[11];
    const int*   sup = (const int*)d_in[12];
    const int*   sdp = (const int*)d_in[13];
    float* y = (float*)d_out;

    cudaFuncSetAttribute(mma_gemm1, cudaFuncAttributeMaxDynamicSharedMemorySize, SM1);
    cudaFuncSetAttribute(mma_gemm2, cudaFuncAttributeMaxDynamicSharedMemorySize, SM2);

    routing_kernel<<<T_ / 8, 256>>>(x, gw);
    dispatch_kernel<<<2, 1024>>>();
    zero_y_kernel<<<(T_ * H_ / 4) / 512, 512>>>((float4*)y);
    xcvt_kernel<<<(T_ * H_ / 4) / 512, 512>>>((const float4*)x);

    mma_gemm1<<<dim3(I_ / 128, E_ + T_ / 128), 512, SM1>>>(
        x, gpk, gsc, upk, usc, sgp, sgs, sup, sus);

    mma_gemm2<<<dim3(H_ / 128, E_ + T_ / 128), 512, SM2>>>(
        dpk, dsc, sdp, sds, y);
}